// round 1
// baseline (speedup 1.0000x reference)
#include <cuda_runtime.h>
#include <math.h>

#define BSZ 16
#define HW 12544
#define C1 256
#define C2 512
#define TT 32
#define HID 512
#define VOC 32000

// ---------------- scratch (static device arrays; no allocation) ----------------
__device__ float  g_conv1[(size_t)BSZ*C1*HW];
__device__ float  g_dw   [(size_t)BSZ*C1*HW];
__device__ float  g_pw   [(size_t)BSZ*C2*HW];
__device__ double g_part [C2*BSZ*2];
__device__ float  g_scale1[C1], g_shift1[C1];
__device__ float  g_scale2[C2], g_shift2[C2];
__device__ float  g_pooled[BSZ*C2], g_t1[BSZ*128], g_f[BSZ*C2], g_feats[BSZ*C2], g_ctx[BSZ*C2];
__device__ float  g_embs[512*512];
__device__ float  g_gctx[BSZ*1536];
__device__ float  g_gi  [(size_t)BSZ*TT*1536];
__device__ float  g_hall[(size_t)BSZ*TT*HID];

// ---------------- conv1: 3->256, 3x3 s2 p1, 224 -> 112 ----------------
__global__ void conv1_kernel(const float* __restrict__ img, const float* __restrict__ w,
                             float* __restrict__ out) {
    __shared__ float ws[C1*27];
    int b = blockIdx.y;
    int tY = blockIdx.x / 7, tX = blockIdx.x % 7;
    for (int i = threadIdx.x; i < C1*27; i += 256) ws[i] = w[i];
    __syncthreads();
    int ty = threadIdx.x >> 4, tx = threadIdx.x & 15;
    int oy = tY*16 + ty, ox = tX*16 + tx;
    int iy0 = oy*2 - 1, ix0 = ox*2 - 1;
    const float* ip = img + (size_t)b*3*224*224;
    float v[27];
#pragma unroll
    for (int ci = 0; ci < 3; ci++)
#pragma unroll
        for (int ky = 0; ky < 3; ky++)
#pragma unroll
            for (int kx = 0; kx < 3; kx++) {
                int iy = iy0 + ky, ix = ix0 + kx;
                float t = 0.f;
                if (iy >= 0 && iy < 224 && ix >= 0 && ix < 224)
                    t = ip[(ci*224 + iy)*224 + ix];
                v[ci*9 + ky*3 + kx] = t;
            }
    size_t obase = (size_t)b*C1*HW + oy*112 + ox;
    for (int c = 0; c < C1; c++) {
        float acc = 0.f;
#pragma unroll
        for (int k = 0; k < 27; k++) acc += v[k] * ws[c*27 + k];
        out[obase + (size_t)c*HW] = acc;
    }
}

// ---------------- per-channel stats (two-stage, deterministic, double) ----------------
__global__ void chan_partial(const float* __restrict__ x, int C, double* __restrict__ part) {
    int c = blockIdx.x, b = blockIdx.y;
    const float* p = x + ((size_t)b*C + c)*HW;
    double s = 0, s2 = 0;
    for (int i = threadIdx.x; i < HW; i += 256) { double v = p[i]; s += v; s2 += v*v; }
    __shared__ double sh[256], sh2[256];
    sh[threadIdx.x] = s; sh2[threadIdx.x] = s2; __syncthreads();
    for (int o = 128; o; o >>= 1) {
        if (threadIdx.x < o) { sh[threadIdx.x] += sh[threadIdx.x+o]; sh2[threadIdx.x] += sh2[threadIdx.x+o]; }
        __syncthreads();
    }
    if (threadIdx.x == 0) { part[(c*BSZ + b)*2] = sh[0]; part[(c*BSZ + b)*2 + 1] = sh2[0]; }
}

__global__ void chan_finalize(int C, const double* __restrict__ part,
                              const float* __restrict__ g, const float* __restrict__ bt,
                              float* __restrict__ scale, float* __restrict__ shift) {
    int c = blockIdx.x*blockDim.x + threadIdx.x;
    if (c >= C) return;
    double s = 0, s2 = 0;
    for (int b = 0; b < BSZ; b++) { s += part[(c*BSZ+b)*2]; s2 += part[(c*BSZ+b)*2 + 1]; }
    double cnt = (double)BSZ * HW;
    double m = s / cnt;
    double var = s2 / cnt - m*m;
    float rs = (float)(1.0 / sqrt(var + 1e-5));
    float sc = g[c] * rs;
    scale[c] = sc;
    shift[c] = bt[c] - (float)m * sc;
}

// ---------------- depthwise 3x3 s1 p1 with fused BN1+ReLU on the input ----------------
__global__ void dw_kernel(const float* __restrict__ in, const float* __restrict__ w,
                          const float* __restrict__ scale, const float* __restrict__ shift,
                          float* __restrict__ out) {
    int tY = blockIdx.x / 7, tX = blockIdx.x % 7;
    int c = blockIdx.y, b = blockIdx.z;
    __shared__ float s[18][19];
    float sc = scale[c], sh = shift[c];
    const float* ip = in + ((size_t)b*C1 + c)*HW;
    for (int i = threadIdx.x; i < 18*18; i += 256) {
        int ly = i / 18, lx = i % 18;
        int y = tY*16 + ly - 1, x = tX*16 + lx - 1;
        float v = 0.f;
        if (y >= 0 && y < 112 && x >= 0 && x < 112) {
            float t = ip[y*112 + x] * sc + sh;
            v = t > 0.f ? t : 0.f;
        }
        s[ly][lx] = v;
    }
    __syncthreads();
    float wv[9];
#pragma unroll
    for (int k = 0; k < 9; k++) wv[k] = w[c*9 + k];
    int ty = threadIdx.x >> 4, tx = threadIdx.x & 15;
    float acc = 0.f;
#pragma unroll
    for (int ky = 0; ky < 3; ky++)
#pragma unroll
        for (int kx = 0; kx < 3; kx++) acc += s[ty+ky][tx+kx] * wv[ky*3 + kx];
    out[((size_t)b*C1 + c)*HW + (tY*16+ty)*112 + tX*16 + tx] = acc;
}

// ---------------- 128x128x8 SGEMM, C = A[MxK] @ B[KxN]  (batched over z) ----------------
__global__ void sgemm_nn(const float* __restrict__ A, const float* __restrict__ B,
                         float* __restrict__ C, int M, int N, int K,
                         size_t strideB, size_t strideC) {
    __shared__ float As[8][128];
    __shared__ float Bs[8][128];
    const float* Bb = B + (size_t)blockIdx.z * strideB;
    float* Cb = C + (size_t)blockIdx.z * strideC;
    int m0 = blockIdx.y * 128, n0 = blockIdx.x * 128;
    int tid = threadIdx.x;
    int tr = tid >> 4, tc = tid & 15;
    float acc[8][8];
#pragma unroll
    for (int i = 0; i < 8; i++)
#pragma unroll
        for (int j = 0; j < 8; j++) acc[i][j] = 0.f;
    for (int k0 = 0; k0 < K; k0 += 8) {
#pragma unroll
        for (int r = 0; r < 4; r++) {
            int idx = tid + r*256;
            int i = idx >> 3, kk = idx & 7;
            As[kk][i] = A[(size_t)(m0+i)*K + k0 + kk];
        }
#pragma unroll
        for (int r = 0; r < 4; r++) {
            int idx = tid + r*256;
            int kk = idx >> 7, j = idx & 127;
            Bs[kk][j] = Bb[(size_t)(k0+kk)*N + n0 + j];
        }
        __syncthreads();
#pragma unroll
        for (int kk = 0; kk < 8; kk++) {
            float a[8], bb[8];
#pragma unroll
            for (int i = 0; i < 8; i++) a[i] = As[kk][tr*8 + i];
#pragma unroll
            for (int j = 0; j < 8; j++) bb[j] = Bs[kk][tc*8 + j];
#pragma unroll
            for (int i = 0; i < 8; i++)
#pragma unroll
                for (int j = 0; j < 8; j++) acc[i][j] += a[i]*bb[j];
        }
        __syncthreads();
    }
#pragma unroll
    for (int i = 0; i < 8; i++) {
        size_t row = (size_t)(m0 + tr*8 + i) * N + n0 + tc*8;
#pragma unroll
        for (int j = 0; j < 8; j++) Cb[row + j] = acc[i][j];
    }
}

// ---------------- 128x128x8 SGEMM, C = A[MxK] @ B[NxK]^T (+bias[n], +rowaux[m>>5][n]) ----
__global__ void sgemm_nt(const float* __restrict__ A, const float* __restrict__ B,
                         float* __restrict__ C, int M, int N, int K, int ldb,
                         const float* __restrict__ bias, const float* __restrict__ rowaux) {
    __shared__ float As[8][128];
    __shared__ float Bs[8][128];
    int m0 = blockIdx.y * 128, n0 = blockIdx.x * 128;
    int tid = threadIdx.x;
    int tr = tid >> 4, tc = tid & 15;
    float acc[8][8];
#pragma unroll
    for (int i = 0; i < 8; i++)
#pragma unroll
        for (int j = 0; j < 8; j++) acc[i][j] = 0.f;
    for (int k0 = 0; k0 < K; k0 += 8) {
#pragma unroll
        for (int r = 0; r < 4; r++) {
            int idx = tid + r*256;
            int i = idx >> 3, kk = idx & 7;
            As[kk][i] = A[(size_t)(m0+i)*K + k0 + kk];
        }
#pragma unroll
        for (int r = 0; r < 4; r++) {
            int idx = tid + r*256;
            int j = idx >> 3, kk = idx & 7;
            Bs[kk][j] = B[(size_t)(n0+j)*ldb + k0 + kk];
        }
        __syncthreads();
#pragma unroll
        for (int kk = 0; kk < 8; kk++) {
            float a[8], bb[8];
#pragma unroll
            for (int i = 0; i < 8; i++) a[i] = As[kk][tr*8 + i];
#pragma unroll
            for (int j = 0; j < 8; j++) bb[j] = Bs[kk][tc*8 + j];
#pragma unroll
            for (int i = 0; i < 8; i++)
#pragma unroll
                for (int j = 0; j < 8; j++) acc[i][j] += a[i]*bb[j];
        }
        __syncthreads();
    }
#pragma unroll
    for (int i = 0; i < 8; i++) {
        int m = m0 + tr*8 + i;
        size_t row = (size_t)m * N + n0 + tc*8;
#pragma unroll
        for (int j = 0; j < 8; j++) {
            float v = acc[i][j];
            int n = n0 + tc*8 + j;
            if (bias)   v += bias[n];
            if (rowaux) v += rowaux[(size_t)(m >> 5)*N + n];
            C[row + j] = v;
        }
    }
}

// ---------------- pooled[b][c] = mean_p relu(bn2(pw)) ----------------
__global__ void pooled_kernel(const float* __restrict__ x, const float* __restrict__ scale,
                              const float* __restrict__ shift, float* __restrict__ pooled) {
    int c = blockIdx.x, b = blockIdx.y;
    const float* p = x + ((size_t)b*C2 + c)*HW;
    float sc = scale[c], sh = shift[c];
    double s = 0;
    for (int i = threadIdx.x; i < HW; i += 256) {
        float v = p[i]*sc + sh;
        if (v > 0.f) s += v;
    }
    __shared__ double shm[256];
    shm[threadIdx.x] = s; __syncthreads();
    for (int o = 128; o; o >>= 1) {
        if (threadIdx.x < o) shm[threadIdx.x] += shm[threadIdx.x+o];
        __syncthreads();
    }
    if (threadIdx.x == 0) pooled[b*C2 + c] = (float)(shm[0] / (double)HW);
}

// ---------------- small GEMM: out[b][o] = act( in[b]. W[o, woff:woff+K] + bias ) ----------
// act: 0=none, 1=relu, 2=sigmoid(v)*aux[b][o]
__global__ void small_gemm(const float* __restrict__ in, int K,
                           const float* __restrict__ W, int ldw, int woff,
                           const float* __restrict__ bias, const float* __restrict__ aux,
                           int O, int act, float* __restrict__ out) {
    __shared__ float sin_s[BSZ*512];
    for (int i = threadIdx.x; i < BSZ*K; i += 256) sin_s[i] = in[i];
    __syncthreads();
    int warp = threadIdx.x >> 5, lane = threadIdx.x & 31;
    int o = blockIdx.x*8 + warp;
    float part[BSZ];
#pragma unroll
    for (int b = 0; b < BSZ; b++) part[b] = 0.f;
    for (int k = lane; k < K; k += 32) {
        float wv = W[(size_t)o*ldw + woff + k];
#pragma unroll
        for (int b = 0; b < BSZ; b++) part[b] += wv * sin_s[b*K + k];
    }
#pragma unroll
    for (int b = 0; b < BSZ; b++) {
        float v = part[b];
#pragma unroll
        for (int off = 16; off; off >>= 1) v += __shfl_xor_sync(0xffffffffu, v, off);
        if (lane == b) {
            if (bias) v += bias[o];
            if (act == 1) v = v > 0.f ? v : 0.f;
            else if (act == 2) v = (1.f/(1.f + expf(-v))) * aux[b*O + o];
            out[b*O + o] = v;
        }
    }
}

// ---------------- gather caption embeddings: row = b*32+t ----------------
__global__ void gather_embs(const int* __restrict__ cap, const float* __restrict__ embed,
                            float* __restrict__ embs) {
    int row = blockIdx.x;
    int b = row >> 5, t = row & 31;
    int tok = cap[b*33 + t];
    const float* src = embed + (size_t)tok*HID;
    float* dst = embs + (size_t)row*HID;
    for (int i = threadIdx.x; i < HID; i += blockDim.x) dst[i] = src[i];
}

// ---------------- one GRU step: h_t from h_{t-1}; warp-per-hidden-unit ----------------
__global__ void gru_step(const float* __restrict__ gi, const float* __restrict__ whh,
                         const float* __restrict__ bhh, float* __restrict__ hall, int t) {
    __shared__ float hs[BSZ*HID];
    for (int i = threadIdx.x; i < BSZ*HID; i += 256) {
        int b = i >> 9, j = i & 511;
        hs[i] = (t == 0) ? 0.f : hall[((size_t)(b*TT + t - 1))*HID + j];
    }
    __syncthreads();
    int warp = threadIdx.x >> 5, lane = threadIdx.x & 31;
    int j = blockIdx.x*8 + warp;
    float w0[16], w1[16], w2[16];
#pragma unroll
    for (int i = 0; i < 16; i++) {
        int k = lane + 32*i;
        w0[i] = whh[(size_t)j*HID + k];
        w1[i] = whh[(size_t)(j + 512)*HID + k];
        w2[i] = whh[(size_t)(j + 1024)*HID + k];
    }
    float bhr = bhh[j], bhz = bhh[j + 512], bhn = bhh[j + 1024];
    for (int b = 0; b < BSZ; b++) {
        float pr = 0.f, pz = 0.f, pn = 0.f;
#pragma unroll
        for (int i = 0; i < 16; i++) {
            float hv = hs[b*HID + lane + 32*i];
            pr += hv*w0[i]; pz += hv*w1[i]; pn += hv*w2[i];
        }
#pragma unroll
        for (int o = 16; o; o >>= 1) {
            pr += __shfl_xor_sync(0xffffffffu, pr, o);
            pz += __shfl_xor_sync(0xffffffffu, pz, o);
            pn += __shfl_xor_sync(0xffffffffu, pn, o);
        }
        if (lane == 0) {
            size_t gib = ((size_t)(b*TT + t))*1536;
            float ir = gi[gib + j], iz = gi[gib + 512 + j], inn = gi[gib + 1024 + j];
            float r = 1.f/(1.f + expf(-(ir + pr + bhr)));
            float z = 1.f/(1.f + expf(-(iz + pz + bhz)));
            float n = tanhf(inn + r*(pn + bhn));
            float hp = hs[b*HID + j];
            hall[((size_t)(b*TT + t))*HID + j] = (1.f - z)*n + z*hp;
        }
    }
}

// =======================================================================
extern "C" void kernel_launch(void* const* d_in, const int* in_sizes, int n_in,
                              void* d_out, int out_size) {
    const float* images   = (const float*)d_in[0];
    const int*   captions = (const int*)  d_in[1];
    const float* conv1_w  = (const float*)d_in[2];
    const float* bn1_g    = (const float*)d_in[3];
    const float* bn1_b    = (const float*)d_in[4];
    const float* dw_w     = (const float*)d_in[5];
    const float* pw_w     = (const float*)d_in[6];
    const float* bn2_g    = (const float*)d_in[7];
    const float* bn2_b    = (const float*)d_in[8];
    const float* se_fc1_w = (const float*)d_in[9];
    const float* se_fc2_w = (const float*)d_in[10];
    const float* enc_fc_w = (const float*)d_in[11];
    const float* enc_fc_b = (const float*)d_in[12];
    const float* embed    = (const float*)d_in[13];
    // d_in[14] = q_w (unused), d_in[15] = k_w (unused)
    const float* v_w      = (const float*)d_in[16];
    const float* gru_w_ih = (const float*)d_in[17];
    const float* gru_w_hh = (const float*)d_in[18];
    const float* gru_b_ih = (const float*)d_in[19];
    const float* gru_b_hh = (const float*)d_in[20];
    const float* fc_w     = (const float*)d_in[21];
    const float* fc_b     = (const float*)d_in[22];

    float *conv1buf, *dwbuf, *pwbuf;
    double* part;
    float *scale1, *shift1, *scale2, *shift2;
    float *pooled, *t1, *fbuf, *feats, *ctx, *embs, *gctx, *gi, *hall;
    cudaGetSymbolAddress((void**)&conv1buf, g_conv1);
    cudaGetSymbolAddress((void**)&dwbuf,    g_dw);
    cudaGetSymbolAddress((void**)&pwbuf,    g_pw);
    cudaGetSymbolAddress((void**)&part,     g_part);
    cudaGetSymbolAddress((void**)&scale1,   g_scale1);
    cudaGetSymbolAddress((void**)&shift1,   g_shift1);
    cudaGetSymbolAddress((void**)&scale2,   g_scale2);
    cudaGetSymbolAddress((void**)&shift2,   g_shift2);
    cudaGetSymbolAddress((void**)&pooled,   g_pooled);
    cudaGetSymbolAddress((void**)&t1,       g_t1);
    cudaGetSymbolAddress((void**)&fbuf,     g_f);
    cudaGetSymbolAddress((void**)&feats,    g_feats);
    cudaGetSymbolAddress((void**)&ctx,      g_ctx);
    cudaGetSymbolAddress((void**)&embs,     g_embs);
    cudaGetSymbolAddress((void**)&gctx,     g_gctx);
    cudaGetSymbolAddress((void**)&gi,       g_gi);
    cudaGetSymbolAddress((void**)&hall,     g_hall);

    // encoder
    conv1_kernel<<<dim3(49, BSZ), 256>>>(images, conv1_w, conv1buf);
    chan_partial<<<dim3(C1, BSZ), 256>>>(conv1buf, C1, part);
    chan_finalize<<<1, 256>>>(C1, part, bn1_g, bn1_b, scale1, shift1);
    dw_kernel<<<dim3(49, C1, BSZ), 256>>>(conv1buf, dw_w, scale1, shift1, dwbuf);
    sgemm_nn<<<dim3(98, 4, BSZ), 256>>>(pw_w, dwbuf, pwbuf, C2, HW, C1,
                                        (size_t)C1*HW, (size_t)C2*HW);
    chan_partial<<<dim3(C2, BSZ), 256>>>(pwbuf, C2, part);
    chan_finalize<<<2, 256>>>(C2, part, bn2_g, bn2_b, scale2, shift2);
    pooled_kernel<<<dim3(C2, BSZ), 256>>>(pwbuf, scale2, shift2, pooled);

    // SE + encoder FC + ctx (tiny GEMMs)
    small_gemm<<<16, 256>>>(pooled, 512, se_fc1_w, 512, 0, nullptr, nullptr, 128, 1, t1);
    small_gemm<<<64, 256>>>(t1, 128, se_fc2_w, 128, 0, nullptr, pooled, 512, 2, fbuf);
    small_gemm<<<64, 256>>>(fbuf, 512, enc_fc_w, 512, 0, enc_fc_b, nullptr, 512, 0, feats);
    small_gemm<<<64, 256>>>(feats, 512, v_w, 512, 0, nullptr, nullptr, 512, 0, ctx);

    // decoder: precompute input gates for all timesteps
    small_gemm<<<192, 256>>>(ctx, 512, gru_w_ih, 1024, 512, gru_b_ih, nullptr, 1536, 0, gctx);
    gather_embs<<<512, 256>>>(captions, embed, embs);
    sgemm_nt<<<dim3(12, 4), 256>>>(embs, gru_w_ih, gi, 512, 1536, 512, 1024, nullptr, gctx);

    // sequential recurrence (only h @ W_hh.T is serial)
    for (int t = 0; t < TT; t++)
        gru_step<<<64, 256>>>(gi, gru_w_hh, gru_b_hh, hall, t);

    // batched logits GEMM over all (b, t)
    sgemm_nt<<<dim3(250, 4), 256>>>(hall, fc_w, (float*)d_out, 512, VOC, 512, 512, fc_b, nullptr);
}

// round 4
// speedup vs baseline: 1.8424x; 1.8424x over previous
#include <cuda_runtime.h>
#include <math.h>

#define BSZ 16
#define HW 12544
#define C1 256
#define C2 512
#define TT 32
#define HID 512
#define VOC 32000

// ---------------- scratch (static device arrays; no allocation) ----------------
__device__ float  g_conv1[(size_t)BSZ*C1*HW];
__device__ float  g_dw   [(size_t)BSZ*C1*HW];
__device__ float  g_pw   [(size_t)BSZ*C2*HW];
__device__ double g_part [C2*BSZ*2];
__device__ float  g_scale1[C1], g_shift1[C1];
__device__ float  g_scale2[C2], g_shift2[C2];
__device__ float  g_pooled[BSZ*C2], g_t1[BSZ*128], g_f[BSZ*C2], g_feats[BSZ*C2], g_ctx[BSZ*C2];
__device__ float  g_embs[512*512];
__device__ float  g_gctx[BSZ*1536];
__device__ float  g_gi  [(size_t)BSZ*TT*1536];
__device__ float  g_hall[(size_t)BSZ*TT*HID];

// ---------------- conv1: 3->256, 3x3 s2 p1, 224 -> 112 ----------------
__global__ void conv1_kernel(const float* __restrict__ img, const float* __restrict__ w,
                             float* __restrict__ out) {
    __shared__ float ws[C1*27];
    int b = blockIdx.y;
    int tY = blockIdx.x / 7, tX = blockIdx.x % 7;
    for (int i = threadIdx.x; i < C1*27; i += 256) ws[i] = w[i];
    __syncthreads();
    int ty = threadIdx.x >> 4, tx = threadIdx.x & 15;
    int oy = tY*16 + ty, ox = tX*16 + tx;
    int iy0 = oy*2 - 1, ix0 = ox*2 - 1;
    const float* ip = img + (size_t)b*3*224*224;
    float v[27];
#pragma unroll
    for (int ci = 0; ci < 3; ci++)
#pragma unroll
        for (int ky = 0; ky < 3; ky++)
#pragma unroll
            for (int kx = 0; kx < 3; kx++) {
                int iy = iy0 + ky, ix = ix0 + kx;
                float t = 0.f;
                if (iy >= 0 && iy < 224 && ix >= 0 && ix < 224)
                    t = ip[(ci*224 + iy)*224 + ix];
                v[ci*9 + ky*3 + kx] = t;
            }
    size_t obase = (size_t)b*C1*HW + oy*112 + ox;
    for (int c = 0; c < C1; c++) {
        float acc = 0.f;
#pragma unroll
        for (int k = 0; k < 27; k++) acc += v[k] * ws[c*27 + k];
        out[obase + (size_t)c*HW] = acc;
    }
}

// ---------------- per-channel stats (two-stage, deterministic, double) ----------------
__global__ void chan_partial(const float* __restrict__ x, int C, double* __restrict__ part) {
    int c = blockIdx.x, b = blockIdx.y;
    const float* p = x + ((size_t)b*C + c)*HW;
    double s = 0, s2 = 0;
    for (int i = threadIdx.x; i < HW; i += 256) { double v = p[i]; s += v; s2 += v*v; }
    __shared__ double sh[256], sh2[256];
    sh[threadIdx.x] = s; sh2[threadIdx.x] = s2; __syncthreads();
    for (int o = 128; o; o >>= 1) {
        if (threadIdx.x < o) { sh[threadIdx.x] += sh[threadIdx.x+o]; sh2[threadIdx.x] += sh2[threadIdx.x+o]; }
        __syncthreads();
    }
    if (threadIdx.x == 0) { part[(c*BSZ + b)*2] = sh[0]; part[(c*BSZ + b)*2 + 1] = sh2[0]; }
}

__global__ void chan_finalize(int C, const double* __restrict__ part,
                              const float* __restrict__ g, const float* __restrict__ bt,
                              float* __restrict__ scale, float* __restrict__ shift) {
    int c = blockIdx.x*blockDim.x + threadIdx.x;
    if (c >= C) return;
    double s = 0, s2 = 0;
    for (int b = 0; b < BSZ; b++) { s += part[(c*BSZ+b)*2]; s2 += part[(c*BSZ+b)*2 + 1]; }
    double cnt = (double)BSZ * HW;
    double m = s / cnt;
    double var = s2 / cnt - m*m;
    float rs = (float)(1.0 / sqrt(var + 1e-5));
    float sc = g[c] * rs;
    scale[c] = sc;
    shift[c] = bt[c] - (float)m * sc;
}

// ---------------- depthwise 3x3 s1 p1 (BN1+ReLU fused on input) -------------
// warp-per-row, 4 outputs per lane via float4 + shfl halo, no smem
__global__ void dw_kernel(const float* __restrict__ in, const float* __restrict__ w,
                          const float* __restrict__ scale, const float* __restrict__ shift,
                          float* __restrict__ out) {
    int warp = threadIdx.x >> 5, lane = threadIdx.x & 31;
    int y = blockIdx.x*8 + warp;            // 14 blocks x 8 warps = 112 rows
    int c = blockIdx.y, b = blockIdx.z;
    float sc = scale[c], sh = shift[c];
    const float* ip = in + ((size_t)b*C1 + c)*HW;
    int x0 = lane*4;
    bool inx = (x0 < 112);

    float v[3][4];
    float lft[3], rgt[3];
#pragma unroll
    for (int r = 0; r < 3; r++) {
        int yy = y - 1 + r;
        float4 t = make_float4(0.f, 0.f, 0.f, 0.f);
        if (inx && yy >= 0 && yy < 112)
            t = *(const float4*)&ip[yy*112 + x0];
        v[r][0] = fmaxf(t.x*sc + sh, 0.f);
        v[r][1] = fmaxf(t.y*sc + sh, 0.f);
        v[r][2] = fmaxf(t.z*sc + sh, 0.f);
        v[r][3] = fmaxf(t.w*sc + sh, 0.f);
        // treat out-of-range x as zero regardless
        if (!inx || yy < 0 || yy >= 112) { v[r][0]=v[r][1]=v[r][2]=v[r][3]=0.f; }
        lft[r] = __shfl_up_sync(0xffffffffu, v[r][3], 1);
        if (lane == 0) lft[r] = 0.f;
        rgt[r] = __shfl_down_sync(0xffffffffu, v[r][0], 1);
        if (lane >= 27) rgt[r] = 0.f;
    }
    float wv[9];
#pragma unroll
    for (int k = 0; k < 9; k++) wv[k] = __ldg(&w[c*9 + k]);

    float o0 = 0.f, o1 = 0.f, o2 = 0.f, o3 = 0.f;
#pragma unroll
    for (int r = 0; r < 3; r++) {
        float e0 = lft[r], e1 = v[r][0], e2 = v[r][1], e3 = v[r][2], e4 = v[r][3], e5 = rgt[r];
        float w0 = wv[r*3+0], w1 = wv[r*3+1], w2 = wv[r*3+2];
        o0 += w0*e0 + w1*e1 + w2*e2;
        o1 += w0*e1 + w1*e2 + w2*e3;
        o2 += w0*e2 + w1*e3 + w2*e4;
        o3 += w0*e3 + w1*e4 + w2*e5;
    }
    if (inx) {
        float4 o = make_float4(o0, o1, o2, o3);
        *(float4*)&out[((size_t)b*C1 + c)*HW + y*112 + x0] = o;
    }
}

// ================= 128x128x16 double-buffered SGEMMs ====================
// NN: C[M,N] = A[M,K] @ B[K,N]   (B, C batched over blockIdx.z)
__global__ void __launch_bounds__(256) sgemm_nn(
        const float* __restrict__ A, const float* __restrict__ B,
        float* __restrict__ C, int M, int N, int K,
        size_t strideB, size_t strideC) {
    __shared__ float As[2][16][128];
    __shared__ float Bs[2][16][128];
    const float* Bb = B + (size_t)blockIdx.z * strideB;
    float* Cb = C + (size_t)blockIdx.z * strideC;
    int m0 = blockIdx.y * 128, n0 = blockIdx.x * 128;
    int tid = threadIdx.x;
    int tr = tid >> 4, tc = tid & 15;
    float acc[8][8];
#pragma unroll
    for (int i = 0; i < 8; i++)
#pragma unroll
        for (int j = 0; j < 8; j++) acc[i][j] = 0.f;

    int KT = K >> 4;
    // prologue: load tile 0 into buffer 0
    {
#pragma unroll
        for (int r = 0; r < 2; r++) {
            int f = tid + r*256;
            int row = f >> 2, kq = f & 3;
            float4 t = *(const float4*)&A[(size_t)(m0+row)*K + kq*4];
            As[0][kq*4+0][row] = t.x; As[0][kq*4+1][row] = t.y;
            As[0][kq*4+2][row] = t.z; As[0][kq*4+3][row] = t.w;
        }
#pragma unroll
        for (int r = 0; r < 2; r++) {
            int f = tid + r*256;
            int kk = f >> 5, nq = f & 31;
            *(float4*)&Bs[0][kk][nq*4] = *(const float4*)&Bb[(size_t)kk*N + n0 + nq*4];
        }
    }
    __syncthreads();

    for (int kt = 0; kt < KT; kt++) {
        int cur = kt & 1, nxt = cur ^ 1;
        float4 pa[2], pb[2];
        if (kt + 1 < KT) {
            int k0 = (kt+1) << 4;
#pragma unroll
            for (int r = 0; r < 2; r++) {
                int f = tid + r*256;
                pa[r] = *(const float4*)&A[(size_t)(m0 + (f>>2))*K + k0 + (f&3)*4];
            }
#pragma unroll
            for (int r = 0; r < 2; r++) {
                int f = tid + r*256;
                pb[r] = *(const float4*)&Bb[(size_t)(k0 + (f>>5))*N + n0 + (f&31)*4];
            }
        }
#pragma unroll
        for (int kk = 0; kk < 16; kk++) {
            float a[8], bb[8];
            *(float4*)&a[0] = *(float4*)&As[cur][kk][tr*8];
            *(float4*)&a[4] = *(float4*)&As[cur][kk][tr*8+4];
            *(float4*)&bb[0] = *(float4*)&Bs[cur][kk][tc*8];
            *(float4*)&bb[4] = *(float4*)&Bs[cur][kk][tc*8+4];
#pragma unroll
            for (int i = 0; i < 8; i++)
#pragma unroll
                for (int j = 0; j < 8; j++) acc[i][j] += a[i]*bb[j];
        }
        if (kt + 1 < KT) {
#pragma unroll
            for (int r = 0; r < 2; r++) {
                int f = tid + r*256;
                int row = f >> 2, kq = f & 3;
                As[nxt][kq*4+0][row] = pa[r].x; As[nxt][kq*4+1][row] = pa[r].y;
                As[nxt][kq*4+2][row] = pa[r].z; As[nxt][kq*4+3][row] = pa[r].w;
            }
#pragma unroll
            for (int r = 0; r < 2; r++) {
                int f = tid + r*256;
                *(float4*)&Bs[nxt][f>>5][(f&31)*4] = pb[r];
            }
        }
        __syncthreads();
    }
#pragma unroll
    for (int i = 0; i < 8; i++) {
        size_t row = (size_t)(m0 + tr*8 + i) * N + n0 + tc*8;
        *(float4*)&Cb[row]   = make_float4(acc[i][0], acc[i][1], acc[i][2], acc[i][3]);
        *(float4*)&Cb[row+4] = make_float4(acc[i][4], acc[i][5], acc[i][6], acc[i][7]);
    }
}

// NT: C[M,N] = A[M,K] @ B[N,K]^T  (+bias[n], +rowaux[(m>>5)][n])
__global__ void __launch_bounds__(256) sgemm_nt(
        const float* __restrict__ A, const float* __restrict__ B,
        float* __restrict__ C, int M, int N, int K, int ldb,
        const float* __restrict__ bias, const float* __restrict__ rowaux) {
    __shared__ float As[2][16][128];
    __shared__ float Bs[2][16][128];
    int m0 = blockIdx.y * 128, n0 = blockIdx.x * 128;
    int tid = threadIdx.x;
    int tr = tid >> 4, tc = tid & 15;
    float acc[8][8];
#pragma unroll
    for (int i = 0; i < 8; i++)
#pragma unroll
        for (int j = 0; j < 8; j++) acc[i][j] = 0.f;

    int KT = K >> 4;
    {
#pragma unroll
        for (int r = 0; r < 2; r++) {
            int f = tid + r*256;
            int row = f >> 2, kq = f & 3;
            float4 t = *(const float4*)&A[(size_t)(m0+row)*K + kq*4];
            As[0][kq*4+0][row] = t.x; As[0][kq*4+1][row] = t.y;
            As[0][kq*4+2][row] = t.z; As[0][kq*4+3][row] = t.w;
        }
#pragma unroll
        for (int r = 0; r < 2; r++) {
            int f = tid + r*256;
            int row = f >> 2, kq = f & 3;
            float4 t = *(const float4*)&B[(size_t)(n0+row)*ldb + kq*4];
            Bs[0][kq*4+0][row] = t.x; Bs[0][kq*4+1][row] = t.y;
            Bs[0][kq*4+2][row] = t.z; Bs[0][kq*4+3][row] = t.w;
        }
    }
    __syncthreads();

    for (int kt = 0; kt < KT; kt++) {
        int cur = kt & 1, nxt = cur ^ 1;
        float4 pa[2], pb[2];
        if (kt + 1 < KT) {
            int k0 = (kt+1) << 4;
#pragma unroll
            for (int r = 0; r < 2; r++) {
                int f = tid + r*256;
                pa[r] = *(const float4*)&A[(size_t)(m0 + (f>>2))*K + k0 + (f&3)*4];
                pb[r] = *(const float4*)&B[(size_t)(n0 + (f>>2))*ldb + k0 + (f&3)*4];
            }
        }
#pragma unroll
        for (int kk = 0; kk < 16; kk++) {
            float a[8], bb[8];
            *(float4*)&a[0] = *(float4*)&As[cur][kk][tr*8];
            *(float4*)&a[4] = *(float4*)&As[cur][kk][tr*8+4];
            *(float4*)&bb[0] = *(float4*)&Bs[cur][kk][tc*8];
            *(float4*)&bb[4] = *(float4*)&Bs[cur][kk][tc*8+4];
#pragma unroll
            for (int i = 0; i < 8; i++)
#pragma unroll
                for (int j = 0; j < 8; j++) acc[i][j] += a[i]*bb[j];
        }
        if (kt + 1 < KT) {
#pragma unroll
            for (int r = 0; r < 2; r++) {
                int f = tid + r*256;
                int row = f >> 2, kq = f & 3;
                As[nxt][kq*4+0][row] = pa[r].x; As[nxt][kq*4+1][row] = pa[r].y;
                As[nxt][kq*4+2][row] = pa[r].z; As[nxt][kq*4+3][row] = pa[r].w;
                Bs[nxt][kq*4+0][row] = pb[r].x; Bs[nxt][kq*4+1][row] = pb[r].y;
                Bs[nxt][kq*4+2][row] = pb[r].z; Bs[nxt][kq*4+3][row] = pb[r].w;
            }
        }
        __syncthreads();
    }
#pragma unroll
    for (int i = 0; i < 8; i++) {
        int m = m0 + tr*8 + i;
        size_t row = (size_t)m * N + n0 + tc*8;
#pragma unroll
        for (int j = 0; j < 8; j++) {
            float v = acc[i][j];
            int n = n0 + tc*8 + j;
            if (bias)   v += bias[n];
            if (rowaux) v += rowaux[(size_t)(m >> 5)*N + n];
            C[row + j] = v;
        }
    }
}

// ---------------- pooled[b][c] = mean_p relu(bn2(pw)) ----------------
__global__ void pooled_kernel(const float* __restrict__ x, const float* __restrict__ scale,
                              const float* __restrict__ shift, float* __restrict__ pooled) {
    int c = blockIdx.x, b = blockIdx.y;
    const float* p = x + ((size_t)b*C2 + c)*HW;
    float sc = scale[c], sh = shift[c];
    double s = 0;
    for (int i = threadIdx.x; i < HW; i += 256) {
        float v = p[i]*sc + sh;
        if (v > 0.f) s += v;
    }
    __shared__ double shm[256];
    shm[threadIdx.x] = s; __syncthreads();
    for (int o = 128; o; o >>= 1) {
        if (threadIdx.x < o) shm[threadIdx.x] += shm[threadIdx.x+o];
        __syncthreads();
    }
    if (threadIdx.x == 0) pooled[b*C2 + c] = (float)(shm[0] / (double)HW);
}

// ---------------- small GEMM: out[b][o] = act( in[b]. W[o, woff:woff+K] + bias ) ----------
// act: 0=none, 1=relu, 2=sigmoid(v)*aux[b][o]
__global__ void small_gemm(const float* __restrict__ in, int K,
                           const float* __restrict__ W, int ldw, int woff,
                           const float* __restrict__ bias, const float* __restrict__ aux,
                           int O, int act, float* __restrict__ out) {
    __shared__ float sin_s[BSZ*512];
    for (int i = threadIdx.x; i < BSZ*K; i += 256) sin_s[i] = in[i];
    __syncthreads();
    int warp = threadIdx.x >> 5, lane = threadIdx.x & 31;
    int o = blockIdx.x*8 + warp;
    float part[BSZ];
#pragma unroll
    for (int b = 0; b < BSZ; b++) part[b] = 0.f;
    for (int k = lane; k < K; k += 32) {
        float wv = W[(size_t)o*ldw + woff + k];
#pragma unroll
        for (int b = 0; b < BSZ; b++) part[b] += wv * sin_s[b*K + k];
    }
#pragma unroll
    for (int b = 0; b < BSZ; b++) {
        float v = part[b];
#pragma unroll
        for (int off = 16; off; off >>= 1) v += __shfl_xor_sync(0xffffffffu, v, off);
        if (lane == b) {
            if (bias) v += bias[o];
            if (act == 1) v = v > 0.f ? v : 0.f;
            else if (act == 2) v = (1.f/(1.f + expf(-v))) * aux[b*O + o];
            out[b*O + o] = v;
        }
    }
}

// ---------------- gather caption embeddings: row = b*32+t ----------------
__global__ void gather_embs(const int* __restrict__ cap, const float* __restrict__ embed,
                            float* __restrict__ embs) {
    int row = blockIdx.x;
    int b = row >> 5, t = row & 31;
    int tok = cap[b*33 + t];
    const float* src = embed + (size_t)tok*HID;
    float* dst = embs + (size_t)row*HID;
    for (int i = threadIdx.x; i < HID; i += blockDim.x) dst[i] = src[i];
}

// ---------------- one GRU step: h_t from h_{t-1}; warp-per-hidden-unit ----------------
__global__ void gru_step(const float* __restrict__ gi, const float* __restrict__ whh,
                         const float* __restrict__ bhh, float* __restrict__ hall, int t) {
    __shared__ float hs[BSZ*HID];
    for (int i = threadIdx.x; i < BSZ*HID; i += 256) {
        int b = i >> 9, j = i & 511;
        hs[i] = (t == 0) ? 0.f : hall[((size_t)(b*TT + t - 1))*HID + j];
    }
    __syncthreads();
    int warp = threadIdx.x >> 5, lane = threadIdx.x & 31;
    int j = blockIdx.x*8 + warp;
    float w0[16], w1[16], w2[16];
#pragma unroll
    for (int i = 0; i < 16; i++) {
        int k = lane + 32*i;
        w0[i] = whh[(size_t)j*HID + k];
        w1[i] = whh[(size_t)(j + 512)*HID + k];
        w2[i] = whh[(size_t)(j + 1024)*HID + k];
    }
    float bhr = bhh[j], bhz = bhh[j + 512], bhn = bhh[j + 1024];
    for (int b = 0; b < BSZ; b++) {
        float pr = 0.f, pz = 0.f, pn = 0.f;
#pragma unroll
        for (int i = 0; i < 16; i++) {
            float hv = hs[b*HID + lane + 32*i];
            pr += hv*w0[i]; pz += hv*w1[i]; pn += hv*w2[i];
        }
#pragma unroll
        for (int o = 16; o; o >>= 1) {
            pr += __shfl_xor_sync(0xffffffffu, pr, o);
            pz += __shfl_xor_sync(0xffffffffu, pz, o);
            pn += __shfl_xor_sync(0xffffffffu, pn, o);
        }
        if (lane == 0) {
            size_t gib = ((size_t)(b*TT + t))*1536;
            float ir = gi[gib + j], iz = gi[gib + 512 + j], inn = gi[gib + 1024 + j];
            float r = 1.f/(1.f + expf(-(ir + pr + bhr)));
            float z = 1.f/(1.f + expf(-(iz + pz + bhz)));
            float n = tanhf(inn + r*(pn + bhn));
            float hp = hs[b*HID + j];
            hall[((size_t)(b*TT + t))*HID + j] = (1.f - z)*n + z*hp;
        }
    }
}

// =======================================================================
extern "C" void kernel_launch(void* const* d_in, const int* in_sizes, int n_in,
                              void* d_out, int out_size) {
    const float* images   = (const float*)d_in[0];
    const int*   captions = (const int*)  d_in[1];
    const float* conv1_w  = (const float*)d_in[2];
    const float* bn1_g    = (const float*)d_in[3];
    const float* bn1_b    = (const float*)d_in[4];
    const float* dw_w     = (const float*)d_in[5];
    const float* pw_w     = (const float*)d_in[6];
    const float* bn2_g    = (const float*)d_in[7];
    const float* bn2_b    = (const float*)d_in[8];
    const float* se_fc1_w = (const float*)d_in[9];
    const float* se_fc2_w = (const float*)d_in[10];
    const float* enc_fc_w = (const float*)d_in[11];
    const float* enc_fc_b = (const float*)d_in[12];
    const float* embed    = (const float*)d_in[13];
    // d_in[14] = q_w (unused), d_in[15] = k_w (unused)
    const float* v_w      = (const float*)d_in[16];
    const float* gru_w_ih = (const float*)d_in[17];
    const float* gru_w_hh = (const float*)d_in[18];
    const float* gru_b_ih = (const float*)d_in[19];
    const float* gru_b_hh = (const float*)d_in[20];
    const float* fc_w     = (const float*)d_in[21];
    const float* fc_b     = (const float*)d_in[22];

    float *conv1buf, *dwbuf, *pwbuf;
    double* part;
    float *scale1, *shift1, *scale2, *shift2;
    float *pooled, *t1, *fbuf, *feats, *ctx, *embs, *gctx, *gi, *hall;
    cudaGetSymbolAddress((void**)&conv1buf, g_conv1);
    cudaGetSymbolAddress((void**)&dwbuf,    g_dw);
    cudaGetSymbolAddress((void**)&pwbuf,    g_pw);
    cudaGetSymbolAddress((void**)&part,     g_part);
    cudaGetSymbolAddress((void**)&scale1,   g_scale1);
    cudaGetSymbolAddress((void**)&shift1,   g_shift1);
    cudaGetSymbolAddress((void**)&scale2,   g_scale2);
    cudaGetSymbolAddress((void**)&shift2,   g_shift2);
    cudaGetSymbolAddress((void**)&pooled,   g_pooled);
    cudaGetSymbolAddress((void**)&t1,       g_t1);
    cudaGetSymbolAddress((void**)&fbuf,     g_f);
    cudaGetSymbolAddress((void**)&feats,    g_feats);
    cudaGetSymbolAddress((void**)&ctx,      g_ctx);
    cudaGetSymbolAddress((void**)&embs,     g_embs);
    cudaGetSymbolAddress((void**)&gctx,     g_gctx);
    cudaGetSymbolAddress((void**)&gi,       g_gi);
    cudaGetSymbolAddress((void**)&hall,     g_hall);

    // encoder
    conv1_kernel<<<dim3(49, BSZ), 256>>>(images, conv1_w, conv1buf);
    chan_partial<<<dim3(C1, BSZ), 256>>>(conv1buf, C1, part);
    chan_finalize<<<1, 256>>>(C1, part, bn1_g, bn1_b, scale1, shift1);
    dw_kernel<<<dim3(14, C1, BSZ), 256>>>(conv1buf, dw_w, scale1, shift1, dwbuf);
    sgemm_nn<<<dim3(98, 4, BSZ), 256>>>(pw_w, dwbuf, pwbuf, C2, HW, C1,
                                        (size_t)C1*HW, (size_t)C2*HW);
    chan_partial<<<dim3(C2, BSZ), 256>>>(pwbuf, C2, part);
    chan_finalize<<<2, 256>>>(C2, part, bn2_g, bn2_b, scale2, shift2);
    pooled_kernel<<<dim3(C2, BSZ), 256>>>(pwbuf, scale2, shift2, pooled);

    // SE + encoder FC + ctx (tiny GEMMs)
    small_gemm<<<16, 256>>>(pooled, 512, se_fc1_w, 512, 0, nullptr, nullptr, 128, 1, t1);
    small_gemm<<<64, 256>>>(t1, 128, se_fc2_w, 128, 0, nullptr, pooled, 512, 2, fbuf);
    small_gemm<<<64, 256>>>(fbuf, 512, enc_fc_w, 512, 0, enc_fc_b, nullptr, 512, 0, feats);
    small_gemm<<<64, 256>>>(feats, 512, v_w, 512, 0, nullptr, nullptr, 512, 0, ctx);

    // decoder: precompute input gates for all timesteps
    small_gemm<<<192, 256>>>(ctx, 512, gru_w_ih, 1024, 512, gru_b_ih, nullptr, 1536, 0, gctx);
    gather_embs<<<512, 256>>>(captions, embed, embs);
    sgemm_nt<<<dim3(12, 4), 256>>>(embs, gru_w_ih, gi, 512, 1536, 512, 1024, nullptr, gctx);

    // sequential recurrence (only h @ W_hh.T is serial)
    for (int t = 0; t < TT; t++)
        gru_step<<<64, 256>>>(gi, gru_w_hh, gru_b_hh, hall, t);

    // batched logits GEMM over all (b, t)
    sgemm_nt<<<dim3(250, 4), 256>>>(hall, fc_w, (float*)d_out, 512, VOC, 512, 512, fc_b, nullptr);
}

// round 7
// speedup vs baseline: 2.5146x; 1.3648x over previous
#include <cuda_runtime.h>
#include <cuda_bf16.h>
#include <math.h>
#include <stdint.h>

#define BSZ 16
#define HW 12544
#define C1 256
#define C2 512
#define TT 32
#define HID 512
#define VOC 32000

// ---------------- scratch (static device arrays; no allocation) ----------------
__device__ float  g_conv1[(size_t)BSZ*C1*HW];
__device__ float  g_dw   [(size_t)BSZ*C1*HW];
__device__ float  g_pw   [(size_t)BSZ*C2*HW];
__device__ double g_part [C2*BSZ*2];
__device__ float  g_scale1[C1], g_shift1[C1];
__device__ float  g_scale2[C2], g_shift2[C2];
__device__ float  g_pooled[BSZ*C2], g_t1[BSZ*128], g_f[BSZ*C2], g_feats[BSZ*C2], g_ctx[BSZ*C2];
__device__ float  g_embs[512*512];
__device__ float  g_gctx[BSZ*1536];
__device__ float  g_gi  [(size_t)BSZ*TT*1536];
__device__ float  g_hall[(size_t)BSZ*TT*HID];

// =====================================================================
//        mma.sync (bf16, m16n8k16) split-precision GEMM machinery
// =====================================================================
// D[m][n] = sum_k A[m][k]*B'[n][k], fp32 in/out, 3-pass bf16 hi/lo split.
// CTA tile 128x128, K-tile 64, 256 threads (8 warps, each 32x64).

__device__ __forceinline__ uint32_t smem_u32(const void* p) {
    uint32_t a;
    asm("{ .reg .u64 t; cvta.to.shared.u64 t, %1; cvt.u32.u64 %0, t; }" : "=r"(a) : "l"(p));
    return a;
}

__device__ __forceinline__ void ldsm4(uint32_t* r, uint32_t addr) {
    asm volatile("ldmatrix.sync.aligned.m8n8.x4.shared.b16 {%0,%1,%2,%3}, [%4];"
                 : "=r"(r[0]), "=r"(r[1]), "=r"(r[2]), "=r"(r[3]) : "r"(addr));
}
__device__ __forceinline__ void ldsm4t(uint32_t* r, uint32_t addr) {
    asm volatile("ldmatrix.sync.aligned.m8n8.x4.trans.shared.b16 {%0,%1,%2,%3}, [%4];"
                 : "=r"(r[0]), "=r"(r[1]), "=r"(r[2]), "=r"(r[3]) : "r"(addr));
}
__device__ __forceinline__ void mma16816(float* d, const uint32_t* a,
                                         uint32_t b0, uint32_t b1) {
    asm volatile(
        "mma.sync.aligned.m16n8k16.row.col.f32.bf16.bf16.f32 "
        "{%0,%1,%2,%3}, {%4,%5,%6,%7}, {%8,%9}, {%0,%1,%2,%3};"
        : "+f"(d[0]), "+f"(d[1]), "+f"(d[2]), "+f"(d[3])
        : "r"(a[0]), "r"(a[1]), "r"(a[2]), "r"(a[3]), "r"(b0), "r"(b1));
}
// pack two fp32 -> bf16x2 (lo = first arg)
__device__ __forceinline__ uint32_t pack_bf2(float lo, float hi) {
    uint32_t r;
    asm("cvt.rn.bf16x2.f32 %0, %1, %2;" : "=r"(r) : "f"(hi), "f"(lo));
    return r;
}
// split a float4 into hi/lo bf16x2 pairs and store 8B to each tile
__device__ __forceinline__ void split_store4(float4 v, char* ph, char* pl, uint32_t off) {
    float hx = __bfloat162float(__float2bfloat16(v.x));
    float hy = __bfloat162float(__float2bfloat16(v.y));
    float hz = __bfloat162float(__float2bfloat16(v.z));
    float hw = __bfloat162float(__float2bfloat16(v.w));
    uint32_t h01 = pack_bf2(hx, hy), h23 = pack_bf2(hz, hw);
    uint32_t l01 = pack_bf2(v.x - hx, v.y - hy), l23 = pack_bf2(v.z - hz, v.w - hw);
    *(uint32_t*)(ph + off)     = h01;
    *(uint32_t*)(ph + off + 4) = h23;
    *(uint32_t*)(pl + off)     = l01;
    *(uint32_t*)(pl + off + 4) = l23;
}

#define LDA_B  144          // A / NT-B row stride bytes (72 bf16, pad)
#define LDB_NN 272          // NN-B row stride bytes (136 bf16, pad)
#define ATILE_B 18432       // 128 * 144
#define SMEM_REQ (4*ATILE_B + 1024)

// BTRANS=0: B global [K,N] (NN);  BTRANS=1: B global [N,K] row-major (NT).
template<int BTRANS>
__global__ void __launch_bounds__(256) mma_gemm(
        const float* __restrict__ A, const float* __restrict__ B,
        float* __restrict__ C, int M, int N, int K, int ldb,
        size_t strideB, size_t strideC,
        const float* __restrict__ bias, const float* __restrict__ rowaux) {
    extern __shared__ char dsm[];
    char* base = (char*)((((uintptr_t)dsm) + 1023) & ~(uintptr_t)1023);
    char* AHp = base;
    char* ALp = base + ATILE_B;
    char* BHp = base + 2*ATILE_B;
    char* BLp = base + 3*ATILE_B;
    uint32_t ah_b = smem_u32(AHp), al_b = smem_u32(ALp);
    uint32_t bh_b = smem_u32(BHp), bl_b = smem_u32(BLp);

    const float* Bb = B + (size_t)blockIdx.z * strideB;
    float* Cb = C + (size_t)blockIdx.z * strideC;
    int m0 = blockIdx.y * 128, n0 = blockIdx.x * 128;
    int tid = threadIdx.x;
    int lane = tid & 31, wid = tid >> 5;
    int warp_m = wid & 3, warp_n = wid >> 2;    // 4 x 2 warp grid, warp tile 32x64

    float acc[2][8][4];
#pragma unroll
    for (int i = 0; i < 2; i++)
#pragma unroll
        for (int j = 0; j < 8; j++)
#pragma unroll
            for (int q = 0; q < 4; q++) acc[i][j][q] = 0.f;

    int KT = K >> 6;
    for (int kt = 0; kt < KT; kt++) {
        int k0 = kt << 6;
        __syncthreads();
        // ---- fill A tile [128 rows m][64 k], stride 144B ----
#pragma unroll
        for (int i = 0; i < 8; i++) {
            int idx = tid + i*256;
            int r = idx >> 4, kq = idx & 15;
            float4 v = *(const float4*)&A[(size_t)(m0 + r)*K + k0 + kq*4];
            split_store4(v, AHp, ALp, r*LDA_B + kq*8);
        }
        // ---- fill B tile ----
        if (BTRANS) {   // [n][k] rows, stride 144B
#pragma unroll
            for (int i = 0; i < 8; i++) {
                int idx = tid + i*256;
                int r = idx >> 4, kq = idx & 15;
                float4 v = *(const float4*)&Bb[(size_t)(n0 + r)*ldb + k0 + kq*4];
                split_store4(v, BHp, BLp, r*LDA_B + kq*8);
            }
        } else {        // [k][n] rows (64 rows x 128 n), stride 272B
#pragma unroll
            for (int i = 0; i < 8; i++) {
                int idx = tid + i*256;
                int k = idx >> 5, nq = idx & 31;
                float4 v = *(const float4*)&Bb[(size_t)(k0 + k)*ldb + n0 + nq*4];
                split_store4(v, BHp, BLp, k*LDB_NN + nq*8);
            }
        }
        __syncthreads();

        // ---- compute: 4 k16 steps ----
#pragma unroll
        for (int ks = 0; ks < 4; ks++) {
            int kb = ks*16;
            uint32_t aH[2][4], aL[2][4];
#pragma unroll
            for (int im = 0; im < 2; im++) {
                int row = warp_m*32 + im*16 + (lane & 15);
                uint32_t off = row*LDA_B + (kb + (lane >> 4)*8)*2;
                ldsm4(aH[im], ah_b + off);
                ldsm4(aL[im], al_b + off);
            }
#pragma unroll
            for (int nc = 0; nc < 4; nc++) {
                uint32_t bH[4], bL[4];
                uint32_t b0H0, b0H1, b1H0, b1H1, b0L0, b0L1, b1L0, b1L1;
                if (BTRANS) {
                    int row = warp_n*64 + nc*16 + (lane & 15);
                    uint32_t off = row*LDA_B + (kb + (lane >> 4)*8)*2;
                    ldsm4(bH, bh_b + off);
                    ldsm4(bL, bl_b + off);
                    // frag n0-7: {r0,r2}, n8-15: {r1,r3}
                    b0H0 = bH[0]; b0H1 = bH[2]; b1H0 = bH[1]; b1H1 = bH[3];
                    b0L0 = bL[0]; b0L1 = bL[2]; b1L0 = bL[1]; b1L1 = bL[3];
                } else {
                    int row = kb + (lane & 15);
                    int col = warp_n*64 + nc*16 + (lane >> 4)*8;
                    uint32_t off = row*LDB_NN + col*2;
                    ldsm4t(bH, bh_b + off);
                    ldsm4t(bL, bl_b + off);
                    // frag n0-7: {r0,r1}, n8-15: {r2,r3}
                    b0H0 = bH[0]; b0H1 = bH[1]; b1H0 = bH[2]; b1H1 = bH[3];
                    b0L0 = bL[0]; b0L1 = bL[1]; b1L0 = bL[2]; b1L1 = bL[3];
                }
#pragma unroll
                for (int im = 0; im < 2; im++) {
                    float* a0 = acc[im][nc*2];
                    float* a1 = acc[im][nc*2 + 1];
                    mma16816(a0, aH[im], b0H0, b0H1);
                    mma16816(a0, aH[im], b0L0, b0L1);
                    mma16816(a0, aL[im], b0H0, b0H1);
                    mma16816(a1, aH[im], b1H0, b1H1);
                    mma16816(a1, aH[im], b1L0, b1L1);
                    mma16816(a1, aL[im], b1H0, b1H1);
                }
            }
        }
    }

    // ---- epilogue: direct float2 stores (each quad covers a 32B sector) ----
    int rbase = m0 + warp_m*32 + (lane >> 2);
    int cbase = n0 + warp_n*64 + (lane & 3)*2;
#pragma unroll
    for (int im = 0; im < 2; im++) {
#pragma unroll
        for (int nf = 0; nf < 8; nf++) {
            int m = rbase + im*16;
            int n = cbase + nf*8;
            float v0 = acc[im][nf][0], v1 = acc[im][nf][1];
            float v2 = acc[im][nf][2], v3 = acc[im][nf][3];
            if (bias)   { float b0 = bias[n], b1 = bias[n+1]; v0 += b0; v1 += b1; v2 += b0; v3 += b1; }
            if (rowaux) {
                float r0 = rowaux[(size_t)(m >> 5)*N + n],     r1 = rowaux[(size_t)(m >> 5)*N + n + 1];
                float r2 = rowaux[(size_t)((m+8) >> 5)*N + n], r3 = rowaux[(size_t)((m+8) >> 5)*N + n + 1];
                v0 += r0; v1 += r1; v2 += r2; v3 += r3;
            }
            *(float2*)&Cb[(size_t)m*N + n]       = make_float2(v0, v1);
            *(float2*)&Cb[(size_t)(m+8)*N + n]   = make_float2(v2, v3);
        }
    }
}

// ---------------- conv1: 3->256, 3x3 s2 p1, 224 -> 112 ----------------
__global__ void conv1_kernel(const float* __restrict__ img, const float* __restrict__ w,
                             float* __restrict__ out) {
    __shared__ float ws[C1*27];
    int b = blockIdx.y;
    int tY = blockIdx.x / 7, tX = blockIdx.x % 7;
    for (int i = threadIdx.x; i < C1*27; i += 256) ws[i] = w[i];
    __syncthreads();
    int ty = threadIdx.x >> 4, tx = threadIdx.x & 15;
    int oy = tY*16 + ty, ox = tX*16 + tx;
    int iy0 = oy*2 - 1, ix0 = ox*2 - 1;
    const float* ip = img + (size_t)b*3*224*224;
    float v[27];
#pragma unroll
    for (int ci = 0; ci < 3; ci++)
#pragma unroll
        for (int ky = 0; ky < 3; ky++)
#pragma unroll
            for (int kx = 0; kx < 3; kx++) {
                int iy = iy0 + ky, ix = ix0 + kx;
                float t = 0.f;
                if (iy >= 0 && iy < 224 && ix >= 0 && ix < 224)
                    t = ip[(ci*224 + iy)*224 + ix];
                v[ci*9 + ky*3 + kx] = t;
            }
    size_t obase = (size_t)b*C1*HW + oy*112 + ox;
    for (int c = 0; c < C1; c++) {
        float acc = 0.f;
#pragma unroll
        for (int k = 0; k < 27; k++) acc += v[k] * ws[c*27 + k];
        out[obase + (size_t)c*HW] = acc;
    }
}

// ---------------- per-channel stats (two-stage, deterministic, double) ----------------
__global__ void chan_partial(const float* __restrict__ x, int C, double* __restrict__ part) {
    int c = blockIdx.x, b = blockIdx.y;
    const float* p = x + ((size_t)b*C + c)*HW;
    double s = 0, s2 = 0;
    for (int i = threadIdx.x; i < HW; i += 256) { double v = p[i]; s += v; s2 += v*v; }
    __shared__ double sh[256], sh2[256];
    sh[threadIdx.x] = s; sh2[threadIdx.x] = s2; __syncthreads();
    for (int o = 128; o; o >>= 1) {
        if (threadIdx.x < o) { sh[threadIdx.x] += sh[threadIdx.x+o]; sh2[threadIdx.x] += sh2[threadIdx.x+o]; }
        __syncthreads();
    }
    if (threadIdx.x == 0) { part[(c*BSZ + b)*2] = sh[0]; part[(c*BSZ + b)*2 + 1] = sh2[0]; }
}

__global__ void chan_finalize(int C, const double* __restrict__ part,
                              const float* __restrict__ g, const float* __restrict__ bt,
                              float* __restrict__ scale, float* __restrict__ shift) {
    int c = blockIdx.x*blockDim.x + threadIdx.x;
    if (c >= C) return;
    double s = 0, s2 = 0;
    for (int b = 0; b < BSZ; b++) { s += part[(c*BSZ+b)*2]; s2 += part[(c*BSZ+b)*2 + 1]; }
    double cnt = (double)BSZ * HW;
    double m = s / cnt;
    double var = s2 / cnt - m*m;
    float rs = (float)(1.0 / sqrt(var + 1e-5));
    float sc = g[c] * rs;
    scale[c] = sc;
    shift[c] = bt[c] - (float)m * sc;
}

// ---------------- depthwise 3x3 s1 p1 (BN1+ReLU fused on input) -------------
__global__ void dw_kernel(const float* __restrict__ in, const float* __restrict__ w,
                          const float* __restrict__ scale, const float* __restrict__ shift,
                          float* __restrict__ out) {
    int warp = threadIdx.x >> 5, lane = threadIdx.x & 31;
    int y = blockIdx.x*8 + warp;
    int c = blockIdx.y, b = blockIdx.z;
    float sc = scale[c], sh = shift[c];
    const float* ip = in + ((size_t)b*C1 + c)*HW;
    int x0 = lane*4;
    bool inx = (x0 < 112);

    float v[3][4];
    float lft[3], rgt[3];
#pragma unroll
    for (int r = 0; r < 3; r++) {
        int yy = y - 1 + r;
        float4 t = make_float4(0.f, 0.f, 0.f, 0.f);
        if (inx && yy >= 0 && yy < 112)
            t = *(const float4*)&ip[yy*112 + x0];
        v[r][0] = fmaxf(t.x*sc + sh, 0.f);
        v[r][1] = fmaxf(t.y*sc + sh, 0.f);
        v[r][2] = fmaxf(t.z*sc + sh, 0.f);
        v[r][3] = fmaxf(t.w*sc + sh, 0.f);
        if (!inx || yy < 0 || yy >= 112) { v[r][0]=v[r][1]=v[r][2]=v[r][3]=0.f; }
        lft[r] = __shfl_up_sync(0xffffffffu, v[r][3], 1);
        if (lane == 0) lft[r] = 0.f;
        rgt[r] = __shfl_down_sync(0xffffffffu, v[r][0], 1);
        if (lane >= 27) rgt[r] = 0.f;
    }
    float wv[9];
#pragma unroll
    for (int k = 0; k < 9; k++) wv[k] = __ldg(&w[c*9 + k]);

    float o0 = 0.f, o1 = 0.f, o2 = 0.f, o3 = 0.f;
#pragma unroll
    for (int r = 0; r < 3; r++) {
        float e0 = lft[r], e1 = v[r][0], e2 = v[r][1], e3 = v[r][2], e4 = v[r][3], e5 = rgt[r];
        float w0 = wv[r*3+0], w1 = wv[r*3+1], w2 = wv[r*3+2];
        o0 += w0*e0 + w1*e1 + w2*e2;
        o1 += w0*e1 + w1*e2 + w2*e3;
        o2 += w0*e2 + w1*e3 + w2*e4;
        o3 += w0*e3 + w1*e4 + w2*e5;
    }
    if (inx) {
        float4 o = make_float4(o0, o1, o2, o3);
        *(float4*)&out[((size_t)b*C1 + c)*HW + y*112 + x0] = o;
    }
}

// ---------------- pooled[b][c] = mean_p relu(bn2(pw)) ----------------
__global__ void pooled_kernel(const float* __restrict__ x, const float* __restrict__ scale,
                              const float* __restrict__ shift, float* __restrict__ pooled) {
    int c = blockIdx.x, b = blockIdx.y;
    const float* p = x + ((size_t)b*C2 + c)*HW;
    float sc = scale[c], sh = shift[c];
    double s = 0;
    for (int i = threadIdx.x; i < HW; i += 256) {
        float v = p[i]*sc + sh;
        if (v > 0.f) s += v;
    }
    __shared__ double shm[256];
    shm[threadIdx.x] = s; __syncthreads();
    for (int o = 128; o; o >>= 1) {
        if (threadIdx.x < o) shm[threadIdx.x] += shm[threadIdx.x+o];
        __syncthreads();
    }
    if (threadIdx.x == 0) pooled[b*C2 + c] = (float)(shm[0] / (double)HW);
}

// ---------------- small GEMM: out[b][o] = act( in[b]. W[o, woff:woff+K] + bias ) ----------
__global__ void small_gemm(const float* __restrict__ in, int K,
                           const float* __restrict__ W, int ldw, int woff,
                           const float* __restrict__ bias, const float* __restrict__ aux,
                           int O, int act, float* __restrict__ out) {
    __shared__ float sin_s[BSZ*512];
    for (int i = threadIdx.x; i < BSZ*K; i += 256) sin_s[i] = in[i];
    __syncthreads();
    int warp = threadIdx.x >> 5, lane = threadIdx.x & 31;
    int o = blockIdx.x*8 + warp;
    float part[BSZ];
#pragma unroll
    for (int b = 0; b < BSZ; b++) part[b] = 0.f;
    for (int k = lane; k < K; k += 32) {
        float wv = W[(size_t)o*ldw + woff + k];
#pragma unroll
        for (int b = 0; b < BSZ; b++) part[b] += wv * sin_s[b*K + k];
    }
#pragma unroll
    for (int b = 0; b < BSZ; b++) {
        float v = part[b];
#pragma unroll
        for (int off = 16; off; off >>= 1) v += __shfl_xor_sync(0xffffffffu, v, off);
        if (lane == b) {
            if (bias) v += bias[o];
            if (act == 1) v = v > 0.f ? v : 0.f;
            else if (act == 2) v = (1.f/(1.f + expf(-v))) * aux[b*O + o];
            out[b*O + o] = v;
        }
    }
}

// ---------------- gather caption embeddings: row = b*32+t ----------------
__global__ void gather_embs(const int* __restrict__ cap, const float* __restrict__ embed,
                            float* __restrict__ embs) {
    int row = blockIdx.x;
    int b = row >> 5, t = row & 31;
    int tok = cap[b*33 + t];
    const float* src = embed + (size_t)tok*HID;
    float* dst = embs + (size_t)row*HID;
    for (int i = threadIdx.x; i < HID; i += blockDim.x) dst[i] = src[i];
}

// ---------------- one GRU step: h_t from h_{t-1}; warp-per-hidden-unit ----------------
__global__ void gru_step(const float* __restrict__ gi, const float* __restrict__ whh,
                         const float* __restrict__ bhh, float* __restrict__ hall, int t) {
    __shared__ float hs[BSZ*HID];
    for (int i = threadIdx.x; i < BSZ*HID; i += 256) {
        int b = i >> 9, j = i & 511;
        hs[i] = (t == 0) ? 0.f : hall[((size_t)(b*TT + t - 1))*HID + j];
    }
    __syncthreads();
    int warp = threadIdx.x >> 5, lane = threadIdx.x & 31;
    int j = blockIdx.x*8 + warp;
    float w0[16], w1[16], w2[16];
#pragma unroll
    for (int i = 0; i < 16; i++) {
        int k = lane + 32*i;
        w0[i] = whh[(size_t)j*HID + k];
        w1[i] = whh[(size_t)(j + 512)*HID + k];
        w2[i] = whh[(size_t)(j + 1024)*HID + k];
    }
    float bhr = bhh[j], bhz = bhh[j + 512], bhn = bhh[j + 1024];
    for (int b = 0; b < BSZ; b++) {
        float pr = 0.f, pz = 0.f, pn = 0.f;
#pragma unroll
        for (int i = 0; i < 16; i++) {
            float hv = hs[b*HID + lane + 32*i];
            pr += hv*w0[i]; pz += hv*w1[i]; pn += hv*w2[i];
        }
#pragma unroll
        for (int o = 16; o; o >>= 1) {
            pr += __shfl_xor_sync(0xffffffffu, pr, o);
            pz += __shfl_xor_sync(0xffffffffu, pz, o);
            pn += __shfl_xor_sync(0xffffffffu, pn, o);
        }
        if (lane == 0) {
            size_t gib = ((size_t)(b*TT + t))*1536;
            float ir = gi[gib + j], iz = gi[gib + 512 + j], inn = gi[gib + 1024 + j];
            float r = 1.f/(1.f + expf(-(ir + pr + bhr)));
            float z = 1.f/(1.f + expf(-(iz + pz + bhz)));
            float n = tanhf(inn + r*(pn + bhn));
            float hp = hs[b*HID + j];
            hall[((size_t)(b*TT + t))*HID + j] = (1.f - z)*n + z*hp;
        }
    }
}

// =======================================================================
extern "C" void kernel_launch(void* const* d_in, const int* in_sizes, int n_in,
                              void* d_out, int out_size) {
    const float* images   = (const float*)d_in[0];
    const int*   captions = (const int*)  d_in[1];
    const float* conv1_w  = (const float*)d_in[2];
    const float* bn1_g    = (const float*)d_in[3];
    const float* bn1_b    = (const float*)d_in[4];
    const float* dw_w     = (const float*)d_in[5];
    const float* pw_w     = (const float*)d_in[6];
    const float* bn2_g    = (const float*)d_in[7];
    const float* bn2_b    = (const float*)d_in[8];
    const float* se_fc1_w = (const float*)d_in[9];
    const float* se_fc2_w = (const float*)d_in[10];
    const float* enc_fc_w = (const float*)d_in[11];
    const float* enc_fc_b = (const float*)d_in[12];
    const float* embed    = (const float*)d_in[13];
    // d_in[14] = q_w (unused), d_in[15] = k_w (unused)
    const float* v_w      = (const float*)d_in[16];
    const float* gru_w_ih = (const float*)d_in[17];
    const float* gru_w_hh = (const float*)d_in[18];
    const float* gru_b_ih = (const float*)d_in[19];
    const float* gru_b_hh = (const float*)d_in[20];
    const float* fc_w     = (const float*)d_in[21];
    const float* fc_b     = (const float*)d_in[22];

    float *conv1buf, *dwbuf, *pwbuf;
    double* part;
    float *scale1, *shift1, *scale2, *shift2;
    float *pooled, *t1, *fbuf, *feats, *ctx, *embs, *gctx, *gi, *hall;
    cudaGetSymbolAddress((void**)&conv1buf, g_conv1);
    cudaGetSymbolAddress((void**)&dwbuf,    g_dw);
    cudaGetSymbolAddress((void**)&pwbuf,    g_pw);
    cudaGetSymbolAddress((void**)&part,     g_part);
    cudaGetSymbolAddress((void**)&scale1,   g_scale1);
    cudaGetSymbolAddress((void**)&shift1,   g_shift1);
    cudaGetSymbolAddress((void**)&scale2,   g_scale2);
    cudaGetSymbolAddress((void**)&shift2,   g_shift2);
    cudaGetSymbolAddress((void**)&pooled,   g_pooled);
    cudaGetSymbolAddress((void**)&t1,       g_t1);
    cudaGetSymbolAddress((void**)&fbuf,     g_f);
    cudaGetSymbolAddress((void**)&feats,    g_feats);
    cudaGetSymbolAddress((void**)&ctx,      g_ctx);
    cudaGetSymbolAddress((void**)&embs,     g_embs);
    cudaGetSymbolAddress((void**)&gctx,     g_gctx);
    cudaGetSymbolAddress((void**)&gi,       g_gi);
    cudaGetSymbolAddress((void**)&hall,     g_hall);

    cudaFuncSetAttribute(mma_gemm<0>, cudaFuncAttributeMaxDynamicSharedMemorySize, SMEM_REQ);
    cudaFuncSetAttribute(mma_gemm<1>, cudaFuncAttributeMaxDynamicSharedMemorySize, SMEM_REQ);

    // encoder
    conv1_kernel<<<dim3(49, BSZ), 256>>>(images, conv1_w, conv1buf);
    chan_partial<<<dim3(C1, BSZ), 256>>>(conv1buf, C1, part);
    chan_finalize<<<1, 256>>>(C1, part, bn1_g, bn1_b, scale1, shift1);
    dw_kernel<<<dim3(14, C1, BSZ), 256>>>(conv1buf, dw_w, scale1, shift1, dwbuf);
    // pointwise conv as tensor-core GEMM: pw_w[512,256] @ dwbuf[b][256,12544]
    mma_gemm<0><<<dim3(98, 4, BSZ), 256, SMEM_REQ>>>(pw_w, dwbuf, pwbuf, C2, HW, C1, HW,
                                                     (size_t)C1*HW, (size_t)C2*HW,
                                                     nullptr, nullptr);
    chan_partial<<<dim3(C2, BSZ), 256>>>(pwbuf, C2, part);
    chan_finalize<<<2, 256>>>(C2, part, bn2_g, bn2_b, scale2, shift2);
    pooled_kernel<<<dim3(C2, BSZ), 256>>>(pwbuf, scale2, shift2, pooled);

    // SE + encoder FC + ctx (tiny GEMMs)
    small_gemm<<<16, 256>>>(pooled, 512, se_fc1_w, 512, 0, nullptr, nullptr, 128, 1, t1);
    small_gemm<<<64, 256>>>(t1, 128, se_fc2_w, 128, 0, nullptr, pooled, 512, 2, fbuf);
    small_gemm<<<64, 256>>>(fbuf, 512, enc_fc_w, 512, 0, enc_fc_b, nullptr, 512, 0, feats);
    small_gemm<<<64, 256>>>(feats, 512, v_w, 512, 0, nullptr, nullptr, 512, 0, ctx);

    // decoder: precompute input gates for all timesteps
    small_gemm<<<192, 256>>>(ctx, 512, gru_w_ih, 1024, 512, gru_b_ih, nullptr, 1536, 0, gctx);
    gather_embs<<<512, 256>>>(captions, embed, embs);
    // gi = embs @ W_ih[:, :512]^T + gctx  (NT, rowaux = gctx)
    mma_gemm<1><<<dim3(12, 4, 1), 256, SMEM_REQ>>>(embs, gru_w_ih, gi, 512, 1536, 512, 1024,
                                                   0, 0, nullptr, gctx);

    // sequential recurrence (only h @ W_hh.T is serial)
    for (int t = 0; t < TT; t++)
        gru_step<<<64, 256>>>(gi, gru_w_hh, gru_b_hh, hall, t);

    // batched logits GEMM over all (b, t): hall[512,512] @ fc_w[32000,512]^T + fc_b
    mma_gemm<1><<<dim3(250, 4, 1), 256, SMEM_REQ>>>(hall, fc_w, (float*)d_out, 512, VOC, 512, 512,
                                                    0, 0, fc_b, nullptr);
}

// round 9
// speedup vs baseline: 2.6660x; 1.0602x over previous
#include <cuda_runtime.h>
#include <cuda_bf16.h>
#include <math.h>
#include <stdint.h>

#define BSZ 16
#define HW 12544
#define C1 256
#define C2 512
#define TT 32
#define HID 512
#define VOC 32000

// ---------------- scratch (static device arrays; no allocation) ----------------
__device__ float  g_conv1[(size_t)BSZ*C1*HW];
__device__ float  g_pw   [(size_t)BSZ*C2*HW];
__device__ double g_part [C2*BSZ*2];
__device__ float  g_scale1[C1], g_shift1[C1];
__device__ float  g_scale2[C2], g_shift2[C2];
__device__ float  g_pooled[BSZ*C2], g_t1[BSZ*128], g_f[BSZ*C2], g_feats[BSZ*C2], g_ctx[BSZ*C2];
__device__ float  g_gctx[BSZ*1536];
__device__ float  g_gi  [(size_t)BSZ*TT*1536];
__device__ float  g_hall[(size_t)BSZ*TT*HID];
__device__ int    g_gbar[TT];

// bf16 hi/lo operand planes
__device__ __nv_bfloat16 g_dwh[(size_t)BSZ*C1*HW], g_dwl[(size_t)BSZ*C1*HW];
__device__ __nv_bfloat16 g_pwwh[C2*C1],            g_pwwl[C2*C1];
__device__ __nv_bfloat16 g_fcwh[(size_t)VOC*HID],  g_fcwl[(size_t)VOC*HID];
__device__ __nv_bfloat16 g_wihh[1536*HID],         g_wihl[1536*HID];
__device__ __nv_bfloat16 g_embsh[512*HID],         g_embsl[512*HID];
__device__ __nv_bfloat16 g_hallh[512*HID],         g_halll[512*HID];

// =====================================================================
//                    helpers
// =====================================================================
__device__ __forceinline__ uint32_t smem_u32(const void* p) {
    uint32_t a;
    asm("{ .reg .u64 t; cvta.to.shared.u64 t, %1; cvt.u32.u64 %0, t; }" : "=r"(a) : "l"(p));
    return a;
}
__device__ __forceinline__ void ldsm4(uint32_t* r, uint32_t addr) {
    asm volatile("ldmatrix.sync.aligned.m8n8.x4.shared.b16 {%0,%1,%2,%3}, [%4];"
                 : "=r"(r[0]), "=r"(r[1]), "=r"(r[2]), "=r"(r[3]) : "r"(addr));
}
__device__ __forceinline__ void ldsm4t(uint32_t* r, uint32_t addr) {
    asm volatile("ldmatrix.sync.aligned.m8n8.x4.trans.shared.b16 {%0,%1,%2,%3}, [%4];"
                 : "=r"(r[0]), "=r"(r[1]), "=r"(r[2]), "=r"(r[3]) : "r"(addr));
}
__device__ __forceinline__ void mma16816(float* d, const uint32_t* a,
                                         uint32_t b0, uint32_t b1) {
    asm volatile(
        "mma.sync.aligned.m16n8k16.row.col.f32.bf16.bf16.f32 "
        "{%0,%1,%2,%3}, {%4,%5,%6,%7}, {%8,%9}, {%0,%1,%2,%3};"
        : "+f"(d[0]), "+f"(d[1]), "+f"(d[2]), "+f"(d[3])
        : "r"(a[0]), "r"(a[1]), "r"(a[2]), "r"(a[3]), "r"(b0), "r"(b1));
}
__device__ __forceinline__ uint32_t pack_bf2(float lo, float hi) {
    uint32_t r;
    asm("cvt.rn.bf16x2.f32 %0, %1, %2;" : "=r"(r) : "f"(hi), "f"(lo));
    return r;
}
__device__ __forceinline__ void split2(float x, float& h, float& l) {
    h = __bfloat162float(__float2bfloat16(x));
    l = x - h;
}
__device__ __forceinline__ void cpa16(uint32_t dst, const void* src) {
    asm volatile("cp.async.cg.shared.global [%0], [%1], 16;" :: "r"(dst), "l"(src));
}
__device__ __forceinline__ void cp_commit() { asm volatile("cp.async.commit_group;"); }
template<int NW> __device__ __forceinline__ void cp_wait() {
    asm volatile("cp.async.wait_group %0;" :: "n"(NW));
}

// =====================================================================
//   split kernels: fp32 -> bf16 hi/lo planes
// =====================================================================
__global__ void split_mat(const float* __restrict__ src, __nv_bfloat16* __restrict__ dh,
                          __nv_bfloat16* __restrict__ dl, size_t n) {
    size_t i = ((size_t)blockIdx.x*256 + threadIdx.x)*4;
    if (i + 3 >= n + 3) return;
    if (i + 3 < n + 0 || i + 3 <= n - 1 + 0) {}   // no-op
    if (i >= n) return;
    float4 v = *(const float4*)&src[i];
    float hx, lx, hy, ly, hz, lz, hw, lw;
    split2(v.x, hx, lx); split2(v.y, hy, ly); split2(v.z, hz, lz); split2(v.w, hw, lw);
    uint2 ho = make_uint2(pack_bf2(hx, hy), pack_bf2(hz, hw));
    uint2 lo = make_uint2(pack_bf2(lx, ly), pack_bf2(lz, lw));
    *(uint2*)&dh[i] = ho;
    *(uint2*)&dl[i] = lo;
}

// strided source: rows x 512 cols, src row stride ld
__global__ void split_strided(const float* __restrict__ src, int ld,
                              __nv_bfloat16* __restrict__ dh, __nv_bfloat16* __restrict__ dl) {
    size_t i = ((size_t)blockIdx.x*256 + threadIdx.x)*4;
    int row = (int)(i >> 9), col = (int)(i & 511);
    float4 v = *(const float4*)&src[(size_t)row*ld + col];
    float hx, lx, hy, ly, hz, lz, hw, lw;
    split2(v.x, hx, lx); split2(v.y, hy, ly); split2(v.z, hz, lz); split2(v.w, hw, lw);
    *(uint2*)&dh[i] = make_uint2(pack_bf2(hx, hy), pack_bf2(hz, hw));
    *(uint2*)&dl[i] = make_uint2(pack_bf2(lx, ly), pack_bf2(lz, lw));
}

// =====================================================================
//   mma.sync GEMM, cp.async double-buffered, pre-split bf16 operands
//   D[m][n] = sum_k A[m][k]*B'[n][k] (3-pass hi/lo), fp32 out.
//   CTA 128x128, K-stage 32, 256 thr (8 warps of 32x64).
// =====================================================================
#define KTILE 32
#define LDA   80            // bytes per k-row (32 bf16 + pad)
#define LDBNN 272           // bytes per n-row (128 bf16 + pad)
#define PLANE 10240         // 128*80 (covers NN-B 32*272=8704 too)
#define STAGE (4*PLANE)
#define SMEM_REQ (2*STAGE + 1024)

template<int BTRANS>
__global__ void __launch_bounds__(256) mma_gemm(
        const __nv_bfloat16* __restrict__ Ah, const __nv_bfloat16* __restrict__ Al,
        const __nv_bfloat16* __restrict__ Bh, const __nv_bfloat16* __restrict__ Bl,
        float* __restrict__ C, int M, int N, int K, int ldb,
        size_t strideB, size_t strideC,
        const float* __restrict__ bias, const float* __restrict__ rowaux) {
    extern __shared__ char dsm[];
    char* base = (char*)((((uintptr_t)dsm) + 1023) & ~(uintptr_t)1023);
    uint32_t sb0 = smem_u32(base);

    const __nv_bfloat16* Bhb = Bh + (size_t)blockIdx.z * strideB;
    const __nv_bfloat16* Blb = Bl + (size_t)blockIdx.z * strideB;
    float* Cb = C + (size_t)blockIdx.z * strideC;
    int m0 = blockIdx.y * 128, n0 = blockIdx.x * 128;
    int tid = threadIdx.x;
    int lane = tid & 31, wid = tid >> 5;
    int warp_m = wid & 3, warp_n = wid >> 2;

    float acc[2][8][4];
#pragma unroll
    for (int i = 0; i < 2; i++)
#pragma unroll
        for (int j = 0; j < 8; j++)
#pragma unroll
            for (int q = 0; q < 4; q++) acc[i][j][q] = 0.f;

    int KT = K / KTILE;

    // ---- stage loader ----
    auto load_stage = [&](int s, int kt) {
        uint32_t st = sb0 + s*STAGE;
        uint32_t ah_s = st, al_s = st + PLANE, bh_s = st + 2*PLANE, bl_s = st + 3*PLANE;
        int k0 = kt * KTILE;
#pragma unroll
        for (int i = 0; i < 2; i++) {
            int idx = tid + i*256;
            int row = idx >> 2, kc = idx & 3;
            uint32_t doff = row*LDA + kc*16;
            const __nv_bfloat16* sa = Ah + (size_t)(m0 + row)*K + k0 + kc*8;
            const __nv_bfloat16* sl = Al + (size_t)(m0 + row)*K + k0 + kc*8;
            cpa16(ah_s + doff, sa);
            cpa16(al_s + doff, sl);
        }
        if (BTRANS) {
#pragma unroll
            for (int i = 0; i < 2; i++) {
                int idx = tid + i*256;
                int row = idx >> 2, kc = idx & 3;
                uint32_t doff = row*LDA + kc*16;
                cpa16(bh_s + doff, Bhb + (size_t)(n0 + row)*ldb + k0 + kc*8);
                cpa16(bl_s + doff, Blb + (size_t)(n0 + row)*ldb + k0 + kc*8);
            }
        } else {
#pragma unroll
            for (int i = 0; i < 2; i++) {
                int idx = tid + i*256;
                int row = idx >> 4, c = idx & 15;
                uint32_t doff = row*LDBNN + c*16;
                cpa16(bh_s + doff, Bhb + (size_t)(k0 + row)*ldb + n0 + c*8);
                cpa16(bl_s + doff, Blb + (size_t)(k0 + row)*ldb + n0 + c*8);
            }
        }
        cp_commit();
    };

    load_stage(0, 0);

    for (int kt = 0; kt < KT; kt++) {
        if (kt + 1 < KT) { load_stage((kt + 1) & 1, kt + 1); cp_wait<1>(); }
        else             { cp_wait<0>(); }
        __syncthreads();

        uint32_t st = sb0 + (kt & 1)*STAGE;
        uint32_t ah_b = st, al_b = st + PLANE, bh_b = st + 2*PLANE, bl_b = st + 3*PLANE;
#pragma unroll
        for (int ks = 0; ks < 2; ks++) {
            int kb = ks*16;
            uint32_t aH[2][4], aL[2][4];
#pragma unroll
            for (int im = 0; im < 2; im++) {
                int row = warp_m*32 + im*16 + (lane & 15);
                uint32_t off = row*LDA + (kb + (lane >> 4)*8)*2;
                ldsm4(aH[im], ah_b + off);
                ldsm4(aL[im], al_b + off);
            }
#pragma unroll
            for (int nc = 0; nc < 4; nc++) {
                uint32_t bH[4], bL[4];
                uint32_t b0H0, b0H1, b1H0, b1H1, b0L0, b0L1, b1L0, b1L1;
                if (BTRANS) {
                    int row = warp_n*64 + nc*16 + (lane & 15);
                    uint32_t off = row*LDA + (kb + (lane >> 4)*8)*2;
                    ldsm4(bH, bh_b + off);
                    ldsm4(bL, bl_b + off);
                    b0H0 = bH[0]; b0H1 = bH[2]; b1H0 = bH[1]; b1H1 = bH[3];
                    b0L0 = bL[0]; b0L1 = bL[2]; b1L0 = bL[1]; b1L1 = bL[3];
                } else {
                    int row = kb + (lane & 15);
                    int col = warp_n*64 + nc*16 + (lane >> 4)*8;
                    uint32_t off = row*LDBNN + col*2;
                    ldsm4t(bH, bh_b + off);
                    ldsm4t(bL, bl_b + off);
                    b0H0 = bH[0]; b0H1 = bH[1]; b1H0 = bH[2]; b1H1 = bH[3];
                    b0L0 = bL[0]; b0L1 = bL[1]; b1L0 = bL[2]; b1L1 = bL[3];
                }
#pragma unroll
                for (int im = 0; im < 2; im++) {
                    float* a0 = acc[im][nc*2];
                    float* a1 = acc[im][nc*2 + 1];
                    mma16816(a0, aH[im], b0H0, b0H1);
                    mma16816(a0, aH[im], b0L0, b0L1);
                    mma16816(a0, aL[im], b0H0, b0H1);
                    mma16816(a1, aH[im], b1H0, b1H1);
                    mma16816(a1, aH[im], b1L0, b1L1);
                    mma16816(a1, aL[im], b1H0, b1H1);
                }
            }
        }
        __syncthreads();
    }

    // ---- epilogue: direct float2 stores ----
    int rbase = m0 + warp_m*32 + (lane >> 2);
    int cbase = n0 + warp_n*64 + (lane & 3)*2;
#pragma unroll
    for (int im = 0; im < 2; im++) {
#pragma unroll
        for (int nf = 0; nf < 8; nf++) {
            int m = rbase + im*16;
            int n = cbase + nf*8;
            float v0 = acc[im][nf][0], v1 = acc[im][nf][1];
            float v2 = acc[im][nf][2], v3 = acc[im][nf][3];
            if (bias)   { float b0 = bias[n], b1 = bias[n+1]; v0 += b0; v1 += b1; v2 += b0; v3 += b1; }
            if (rowaux) {
                float r0 = rowaux[(size_t)(m >> 5)*N + n],     r1 = rowaux[(size_t)(m >> 5)*N + n + 1];
                float r2 = rowaux[(size_t)((m+8) >> 5)*N + n], r3 = rowaux[(size_t)((m+8) >> 5)*N + n + 1];
                v0 += r0; v1 += r1; v2 += r2; v3 += r3;
            }
            *(float2*)&Cb[(size_t)m*N + n]     = make_float2(v0, v1);
            *(float2*)&Cb[(size_t)(m+8)*N + n] = make_float2(v2, v3);
        }
    }
}

// ---------------- conv1: 3->256, 3x3 s2 p1, 224 -> 112 ----------------
__global__ void conv1_kernel(const float* __restrict__ img, const float* __restrict__ w,
                             float* __restrict__ out) {
    __shared__ float ws[C1*27];
    int b = blockIdx.y;
    int tY = blockIdx.x / 7, tX = blockIdx.x % 7;
    for (int i = threadIdx.x; i < C1*27; i += 256) ws[i] = w[i];
    __syncthreads();
    int ty = threadIdx.x >> 4, tx = threadIdx.x & 15;
    int oy = tY*16 + ty, ox = tX*16 + tx;
    int iy0 = oy*2 - 1, ix0 = ox*2 - 1;
    const float* ip = img + (size_t)b*3*224*224;
    float v[27];
#pragma unroll
    for (int ci = 0; ci < 3; ci++)
#pragma unroll
        for (int ky = 0; ky < 3; ky++)
#pragma unroll
            for (int kx = 0; kx < 3; kx++) {
                int iy = iy0 + ky, ix = ix0 + kx;
                float t = 0.f;
                if (iy >= 0 && iy < 224 && ix >= 0 && ix < 224)
                    t = ip[(ci*224 + iy)*224 + ix];
                v[ci*9 + ky*3 + kx] = t;
            }
    size_t obase = (size_t)b*C1*HW + oy*112 + ox;
    for (int c = 0; c < C1; c++) {
        float acc = 0.f;
#pragma unroll
        for (int k = 0; k < 27; k++) acc += v[k] * ws[c*27 + k];
        out[obase + (size_t)c*HW] = acc;
    }
}

// ---------------- per-channel stats (two-stage, deterministic, double) ----------------
__global__ void chan_partial(const float* __restrict__ x, int C, double* __restrict__ part) {
    int c = blockIdx.x, b = blockIdx.y;
    const float* p = x + ((size_t)b*C + c)*HW;
    double s = 0, s2 = 0;
    for (int i = threadIdx.x; i < HW; i += 256) { double v = p[i]; s += v; s2 += v*v; }
    __shared__ double sh[256], sh2[256];
    sh[threadIdx.x] = s; sh2[threadIdx.x] = s2; __syncthreads();
    for (int o = 128; o; o >>= 1) {
        if (threadIdx.x < o) { sh[threadIdx.x] += sh[threadIdx.x+o]; sh2[threadIdx.x] += sh2[threadIdx.x+o]; }
        __syncthreads();
    }
    if (threadIdx.x == 0) { part[(c*BSZ + b)*2] = sh[0]; part[(c*BSZ + b)*2 + 1] = sh2[0]; }
}

__global__ void chan_finalize(int C, const double* __restrict__ part,
                              const float* __restrict__ g, const float* __restrict__ bt,
                              float* __restrict__ scale, float* __restrict__ shift) {
    int c = blockIdx.x*blockDim.x + threadIdx.x;
    if (c >= C) return;
    double s = 0, s2 = 0;
    for (int b = 0; b < BSZ; b++) { s += part[(c*BSZ+b)*2]; s2 += part[(c*BSZ+b)*2 + 1]; }
    double cnt = (double)BSZ * HW;
    double m = s / cnt;
    double var = s2 / cnt - m*m;
    float rs = (float)(1.0 / sqrt(var + 1e-5));
    float sc = g[c] * rs;
    scale[c] = sc;
    shift[c] = bt[c] - (float)m * sc;
}

// ---------------- depthwise 3x3 s1 p1 (BN1+ReLU fused), writes bf16 hi/lo ----
__global__ void dw_kernel(const float* __restrict__ in, const float* __restrict__ w,
                          const float* __restrict__ scale, const float* __restrict__ shift,
                          __nv_bfloat16* __restrict__ outh, __nv_bfloat16* __restrict__ outl) {
    int warp = threadIdx.x >> 5, lane = threadIdx.x & 31;
    int y = blockIdx.x*8 + warp;
    int c = blockIdx.y, b = blockIdx.z;
    float sc = scale[c], sh = shift[c];
    const float* ip = in + ((size_t)b*C1 + c)*HW;
    int x0 = lane*4;
    bool inx = (x0 < 112);

    float v[3][4];
    float lft[3], rgt[3];
#pragma unroll
    for (int r = 0; r < 3; r++) {
        int yy = y - 1 + r;
        float4 t = make_float4(0.f, 0.f, 0.f, 0.f);
        if (inx && yy >= 0 && yy < 112)
            t = *(const float4*)&ip[yy*112 + x0];
        v[r][0] = fmaxf(t.x*sc + sh, 0.f);
        v[r][1] = fmaxf(t.y*sc + sh, 0.f);
        v[r][2] = fmaxf(t.z*sc + sh, 0.f);
        v[r][3] = fmaxf(t.w*sc + sh, 0.f);
        if (!inx || yy < 0 || yy >= 112) { v[r][0]=v[r][1]=v[r][2]=v[r][3]=0.f; }
        lft[r] = __shfl_up_sync(0xffffffffu, v[r][3], 1);
        if (lane == 0) lft[r] = 0.f;
        rgt[r] = __shfl_down_sync(0xffffffffu, v[r][0], 1);
        if (lane >= 27) rgt[r] = 0.f;
    }
    float wv[9];
#pragma unroll
    for (int k = 0; k < 9; k++) wv[k] = __ldg(&w[c*9 + k]);

    float o0 = 0.f, o1 = 0.f, o2 = 0.f, o3 = 0.f;
#pragma unroll
    for (int r = 0; r < 3; r++) {
        float e0 = lft[r], e1 = v[r][0], e2 = v[r][1], e3 = v[r][2], e4 = v[r][3], e5 = rgt[r];
        float w0 = wv[r*3+0], w1 = wv[r*3+1], w2 = wv[r*3+2];
        o0 += w0*e0 + w1*e1 + w2*e2;
        o1 += w0*e1 + w1*e2 + w2*e3;
        o2 += w0*e2 + w1*e3 + w2*e4;
        o3 += w0*e3 + w1*e4 + w2*e5;
    }
    if (inx) {
        float h0,l0,h1,l1,h2,l2,h3,l3;
        split2(o0,h0,l0); split2(o1,h1,l1); split2(o2,h2,l2); split2(o3,h3,l3);
        size_t off = ((size_t)b*C1 + c)*HW + y*112 + x0;
        *(uint2*)&outh[off] = make_uint2(pack_bf2(h0,h1), pack_bf2(h2,h3));
        *(uint2*)&outl[off] = make_uint2(pack_bf2(l0,l1), pack_bf2(l2,l3));
    }
}

// ---------------- pooled[b][c] = mean_p relu(bn2(pw)) ----------------
__global__ void pooled_kernel(const float* __restrict__ x, const float* __restrict__ scale,
                              const float* __restrict__ shift, float* __restrict__ pooled) {
    int c = blockIdx.x, b = blockIdx.y;
    const float* p = x + ((size_t)b*C2 + c)*HW;
    float sc = scale[c], sh = shift[c];
    double s = 0;
    for (int i = threadIdx.x; i < HW; i += 256) {
        float v = p[i]*sc + sh;
        if (v > 0.f) s += v;
    }
    __shared__ double shm[256];
    shm[threadIdx.x] = s; __syncthreads();
    for (int o = 128; o; o >>= 1) {
        if (threadIdx.x < o) shm[threadIdx.x] += shm[threadIdx.x+o];
        __syncthreads();
    }
    if (threadIdx.x == 0) pooled[b*C2 + c] = (float)(shm[0] / (double)HW);
}

// ---------------- small GEMM: out[b][o] = act( in[b]. W[o, woff:woff+K] + bias ) ----------
__global__ void small_gemm(const float* __restrict__ in, int K,
                           const float* __restrict__ W, int ldw, int woff,
                           const float* __restrict__ bias, const float* __restrict__ aux,
                           int O, int act, float* __restrict__ out) {
    __shared__ float sin_s[BSZ*512];
    for (int i = threadIdx.x; i < BSZ*K; i += 256) sin_s[i] = in[i];
    __syncthreads();
    int warp = threadIdx.x >> 5, lane = threadIdx.x & 31;
    int o = blockIdx.x*8 + warp;
    float part[BSZ];
#pragma unroll
    for (int b = 0; b < BSZ; b++) part[b] = 0.f;
    for (int k = lane; k < K; k += 32) {
        float wv = W[(size_t)o*ldw + woff + k];
#pragma unroll
        for (int b = 0; b < BSZ; b++) part[b] += wv * sin_s[b*K + k];
    }
#pragma unroll
    for (int b = 0; b < BSZ; b++) {
        float v = part[b];
#pragma unroll
        for (int off = 16; off; off >>= 1) v += __shfl_xor_sync(0xffffffffu, v, off);
        if (lane == b) {
            if (bias) v += bias[o];
            if (act == 1) v = v > 0.f ? v : 0.f;
            else if (act == 2) v = (1.f/(1.f + expf(-v))) * aux[b*O + o];
            out[b*O + o] = v;
        }
    }
}

// ---------------- gather caption embeddings: writes split planes ----------------
__global__ void gather_embs(const int* __restrict__ cap, const float* __restrict__ embed,
                            __nv_bfloat16* __restrict__ eh, __nv_bfloat16* __restrict__ el) {
    int row = blockIdx.x;
    int b = row >> 5, t = row & 31;
    int tok = cap[b*33 + t];
    const float* src = embed + (size_t)tok*HID;
    int i = threadIdx.x*2;     // 256 threads x 2 = 512
    float2 v = *(const float2*)&src[i];
    float h0,l0,h1,l1;
    split2(v.x,h0,l0); split2(v.y,h1,l1);
    *(uint32_t*)&eh[(size_t)row*HID + i] = pack_bf2(h0,h1);
    *(uint32_t*)&el[(size_t)row*HID + i] = pack_bf2(l0,l1);
}

// ---------------- reset barrier counters ----------------
__global__ void gru_reset() {
    if (threadIdx.x < TT) g_gbar[threadIdx.x] = 0;
}

// ---------------- persistent GRU: all TT steps, grid barrier between ----------------
#define GRU_BLKS 64
__global__ void __launch_bounds__(256) gru_persist(
        const float* __restrict__ gi, const float* __restrict__ whh,
        const float* __restrict__ bhh, float* __restrict__ hall,
        __nv_bfloat16* __restrict__ hallh, __nv_bfloat16* __restrict__ halll) {
    __shared__ float hs[BSZ*HID];
    int tid = threadIdx.x;
    int warp = tid >> 5, lane = tid & 31;
    int j = blockIdx.x*8 + warp;
    float w0[16], w1[16], w2[16];
#pragma unroll
    for (int i = 0; i < 16; i++) {
        int k = lane + 32*i;
        w0[i] = whh[(size_t)j*HID + k];
        w1[i] = whh[(size_t)(j + 512)*HID + k];
        w2[i] = whh[(size_t)(j + 1024)*HID + k];
    }
    float bhr = bhh[j], bhz = bhh[j + 512], bhn = bhh[j + 1024];

    for (int t = 0; t < TT; t++) {
        // load h_{t-1}
        for (int i = tid; i < BSZ*HID; i += 256) {
            int b = i >> 9, jj = i & 511;
            hs[i] = (t == 0) ? 0.f : hall[((size_t)(b*TT + t - 1))*HID + jj];
        }
        __syncthreads();
        for (int b = 0; b < BSZ; b++) {
            float pr = 0.f, pz = 0.f, pn = 0.f;
#pragma unroll
            for (int i = 0; i < 16; i++) {
                float hv = hs[b*HID + lane + 32*i];
                pr += hv*w0[i]; pz += hv*w1[i]; pn += hv*w2[i];
            }
#pragma unroll
            for (int o = 16; o; o >>= 1) {
                pr += __shfl_xor_sync(0xffffffffu, pr, o);
                pz += __shfl_xor_sync(0xffffffffu, pz, o);
                pn += __shfl_xor_sync(0xffffffffu, pn, o);
            }
            if (lane == 0) {
                size_t gib = ((size_t)(b*TT + t))*1536;
                float ir = gi[gib + j], iz = gi[gib + 512 + j], inn = gi[gib + 1024 + j];
                float r = 1.f/(1.f + expf(-(ir + pr + bhr)));
                float z = 1.f/(1.f + expf(-(iz + pz + bhz)));
                float n = tanhf(inn + r*(pn + bhn));
                float hp = hs[b*HID + j];
                float hn2 = (1.f - z)*n + z*hp;
                size_t oidx = ((size_t)(b*TT + t))*HID + j;
                hall[oidx] = hn2;
                float hh, hl;
                split2(hn2, hh, hl);
                hallh[oidx] = __float2bfloat16(hh);
                halll[oidx] = __float2bfloat16(hl);
            }
        }
        // grid barrier for step t
        __threadfence();
        __syncthreads();
        if (tid == 0) {
            atomicAdd(&g_gbar[t], 1);
            while (atomicAdd(&g_gbar[t], 0) < GRU_BLKS) __nanosleep(64);
        }
        __syncthreads();
    }
}

// =======================================================================
extern "C" void kernel_launch(void* const* d_in, const int* in_sizes, int n_in,
                              void* d_out, int out_size) {
    const float* images   = (const float*)d_in[0];
    const int*   captions = (const int*)  d_in[1];
    const float* conv1_w  = (const float*)d_in[2];
    const float* bn1_g    = (const float*)d_in[3];
    const float* bn1_b    = (const float*)d_in[4];
    const float* dw_w     = (const float*)d_in[5];
    const float* pw_w     = (const float*)d_in[6];
    const float* bn2_g    = (const float*)d_in[7];
    const float* bn2_b    = (const float*)d_in[8];
    const float* se_fc1_w = (const float*)d_in[9];
    const float* se_fc2_w = (const float*)d_in[10];
    const float* enc_fc_w = (const float*)d_in[11];
    const float* enc_fc_b = (const float*)d_in[12];
    const float* embed    = (const float*)d_in[13];
    // d_in[14] = q_w (unused), d_in[15] = k_w (unused)
    const float* v_w      = (const float*)d_in[16];
    const float* gru_w_ih = (const float*)d_in[17];
    const float* gru_w_hh = (const float*)d_in[18];
    const float* gru_b_ih = (const float*)d_in[19];
    const float* gru_b_hh = (const float*)d_in[20];
    const float* fc_w     = (const float*)d_in[21];
    const float* fc_b     = (const float*)d_in[22];

    float *conv1buf, *pwbuf;
    double* part;
    float *scale1, *shift1, *scale2, *shift2;
    float *pooled, *t1, *fbuf, *feats, *ctx, *gctx, *gi, *hall;
    __nv_bfloat16 *dwh, *dwl, *pwwh, *pwwl, *fcwh, *fcwl, *wihh, *wihl, *embsh, *embsl, *hallh, *halll;
    cudaGetSymbolAddress((void**)&conv1buf, g_conv1);
    cudaGetSymbolAddress((void**)&pwbuf,    g_pw);
    cudaGetSymbolAddress((void**)&part,     g_part);
    cudaGetSymbolAddress((void**)&scale1,   g_scale1);
    cudaGetSymbolAddress((void**)&shift1,   g_shift1);
    cudaGetSymbolAddress((void**)&scale2,   g_scale2);
    cudaGetSymbolAddress((void**)&shift2,   g_shift2);
    cudaGetSymbolAddress((void**)&pooled,   g_pooled);
    cudaGetSymbolAddress((void**)&t1,       g_t1);
    cudaGetSymbolAddress((void**)&fbuf,     g_f);
    cudaGetSymbolAddress((void**)&feats,    g_feats);
    cudaGetSymbolAddress((void**)&ctx,      g_ctx);
    cudaGetSymbolAddress((void**)&gctx,     g_gctx);
    cudaGetSymbolAddress((void**)&gi,       g_gi);
    cudaGetSymbolAddress((void**)&hall,     g_hall);
    cudaGetSymbolAddress((void**)&dwh,      g_dwh);
    cudaGetSymbolAddress((void**)&dwl,      g_dwl);
    cudaGetSymbolAddress((void**)&pwwh,     g_pwwh);
    cudaGetSymbolAddress((void**)&pwwl,     g_pwwl);
    cudaGetSymbolAddress((void**)&fcwh,     g_fcwh);
    cudaGetSymbolAddress((void**)&fcwl,     g_fcwl);
    cudaGetSymbolAddress((void**)&wihh,     g_wihh);
    cudaGetSymbolAddress((void**)&wihl,     g_wihl);
    cudaGetSymbolAddress((void**)&embsh,    g_embsh);
    cudaGetSymbolAddress((void**)&embsl,    g_embsl);
    cudaGetSymbolAddress((void**)&hallh,    g_hallh);
    cudaGetSymbolAddress((void**)&halll,    g_halll);

    cudaFuncSetAttribute(mma_gemm<0>, cudaFuncAttributeMaxDynamicSharedMemorySize, SMEM_REQ);
    cudaFuncSetAttribute(mma_gemm<1>, cudaFuncAttributeMaxDynamicSharedMemorySize, SMEM_REQ);

    // weight splits (independent of encoder)
    split_mat<<<(C2*C1)/1024, 256>>>(pw_w, pwwh, pwwl, (size_t)C2*C1);
    split_mat<<<((size_t)VOC*HID)/1024, 256>>>(fc_w, fcwh, fcwl, (size_t)VOC*HID);
    split_strided<<<(1536*512)/1024, 256>>>(gru_w_ih, 1024, wihh, wihl);

    // encoder
    conv1_kernel<<<dim3(49, BSZ), 256>>>(images, conv1_w, conv1buf);
    chan_partial<<<dim3(C1, BSZ), 256>>>(conv1buf, C1, part);
    chan_finalize<<<1, 256>>>(C1, part, bn1_g, bn1_b, scale1, shift1);
    dw_kernel<<<dim3(14, C1, BSZ), 256>>>(conv1buf, dw_w, scale1, shift1, dwh, dwl);
    // pointwise conv: pw_w[512,256] @ dw[b][256,12544]  (NN)
    mma_gemm<0><<<dim3(98, 4, BSZ), 256, SMEM_REQ>>>(pwwh, pwwl, dwh, dwl, pwbuf,
                                                     C2, HW, C1, HW,
                                                     (size_t)C1*HW, (size_t)C2*HW,
                                                     nullptr, nullptr);
    chan_partial<<<dim3(C2, BSZ), 256>>>(pwbuf, C2, part);
    chan_finalize<<<2, 256>>>(C2, part, bn2_g, bn2_b, scale2, shift2);
    pooled_kernel<<<dim3(C2, BSZ), 256>>>(pwbuf, scale2, shift2, pooled);

    // SE + encoder FC + ctx (tiny GEMMs)
    small_gemm<<<16, 256>>>(pooled, 512, se_fc1_w, 512, 0, nullptr, nullptr, 128, 1, t1);
    small_gemm<<<64, 256>>>(t1, 128, se_fc2_w, 128, 0, nullptr, pooled, 512, 2, fbuf);
    small_gemm<<<64, 256>>>(fbuf, 512, enc_fc_w, 512, 0, enc_fc_b, nullptr, 512, 0, feats);
    small_gemm<<<64, 256>>>(feats, 512, v_w, 512, 0, nullptr, nullptr, 512, 0, ctx);

    // decoder: precompute input gates
    small_gemm<<<192, 256>>>(ctx, 512, gru_w_ih, 1024, 512, gru_b_ih, nullptr, 1536, 0, gctx);
    gather_embs<<<512, 256>>>(captions, embed, embsh, embsl);
    // gi = embs @ W_ih[:, :512]^T + gctx  (NT, rowaux = gctx)
    mma_gemm<1><<<dim3(12, 4, 1), 256, SMEM_REQ>>>(embsh, embsl, wihh, wihl, gi,
                                                   512, 1536, 512, 512,
                                                   0, 0, nullptr, gctx);

    // persistent GRU recurrence
    gru_reset<<<1, 32>>>();
    gru_persist<<<GRU_BLKS, 256>>>(gi, gru_w_hh, gru_b_hh, hall, hallh, halll);

    // logits: hall[512,512] @ fc_w[32000,512]^T + fc_b  (NT)
    mma_gemm<1><<<dim3(250, 4, 1), 256, SMEM_REQ>>>(hallh, halll, fcwh, fcwl, (float*)d_out,
                                                    512, VOC, 512, 512,
                                                    0, 0, fc_b, nullptr);
}

// round 10
// speedup vs baseline: 3.9849x; 1.4947x over previous
#include <cuda_runtime.h>
#include <cuda_bf16.h>
#include <cuda_fp16.h>
#include <math.h>
#include <stdint.h>

#define BSZ 16
#define HW 12544
#define C1 256
#define C2 512
#define TT 32
#define HID 512
#define VOC 32000

// ---------------- scratch (static device arrays; no allocation) ----------------
__device__ float   g_conv1[(size_t)BSZ*C1*HW];
__device__ double  g_part [C2*BSZ*2];
__device__ double2 g_part2[(size_t)C2*BSZ*98];
__device__ float   g_scale1[C1], g_shift1[C1];
__device__ float   g_scale2[C2], g_shift2[C2];
__device__ float   g_pooled[BSZ*C2], g_t1[BSZ*128], g_f[BSZ*C2], g_feats[BSZ*C2], g_ctx[BSZ*C2];
__device__ float   g_gctx[BSZ*1536];
__device__ float   g_gi  [(size_t)BSZ*TT*1536];
__device__ float   g_hall[(size_t)BSZ*TT*HID];
__device__ int     g_gbar[TT];

// fp16 planes for the pointwise-conv GEMM (single pass)
__device__ __half g_dwh[(size_t)BSZ*C1*HW];
__device__ __half g_pwwh[C2*C1];
__device__ __half g_pwout[(size_t)BSZ*C2*HW];
// bf16 hi/lo planes for precision-critical GEMMs (gi, logits)
__device__ __nv_bfloat16 g_fcwh[(size_t)VOC*HID],  g_fcwl[(size_t)VOC*HID];
__device__ __nv_bfloat16 g_wihh[1536*HID],         g_wihl[1536*HID];
__device__ __nv_bfloat16 g_embsh[512*HID],         g_embsl[512*HID];
__device__ __nv_bfloat16 g_hallh[512*HID],         g_halll[512*HID];

// =====================================================================
//                    helpers
// =====================================================================
__device__ __forceinline__ uint32_t smem_u32(const void* p) {
    uint32_t a;
    asm("{ .reg .u64 t; cvta.to.shared.u64 t, %1; cvt.u32.u64 %0, t; }" : "=r"(a) : "l"(p));
    return a;
}
__device__ __forceinline__ void ldsm4(uint32_t* r, uint32_t addr) {
    asm volatile("ldmatrix.sync.aligned.m8n8.x4.shared.b16 {%0,%1,%2,%3}, [%4];"
                 : "=r"(r[0]), "=r"(r[1]), "=r"(r[2]), "=r"(r[3]) : "r"(addr));
}
__device__ __forceinline__ void ldsm4t(uint32_t* r, uint32_t addr) {
    asm volatile("ldmatrix.sync.aligned.m8n8.x4.trans.shared.b16 {%0,%1,%2,%3}, [%4];"
                 : "=r"(r[0]), "=r"(r[1]), "=r"(r[2]), "=r"(r[3]) : "r"(addr));
}
__device__ __forceinline__ void mma_bf(float* d, const uint32_t* a, uint32_t b0, uint32_t b1) {
    asm volatile(
        "mma.sync.aligned.m16n8k16.row.col.f32.bf16.bf16.f32 "
        "{%0,%1,%2,%3}, {%4,%5,%6,%7}, {%8,%9}, {%0,%1,%2,%3};"
        : "+f"(d[0]), "+f"(d[1]), "+f"(d[2]), "+f"(d[3])
        : "r"(a[0]), "r"(a[1]), "r"(a[2]), "r"(a[3]), "r"(b0), "r"(b1));
}
__device__ __forceinline__ void mma_fp(float* d, const uint32_t* a, uint32_t b0, uint32_t b1) {
    asm volatile(
        "mma.sync.aligned.m16n8k16.row.col.f32.f16.f16.f32 "
        "{%0,%1,%2,%3}, {%4,%5,%6,%7}, {%8,%9}, {%0,%1,%2,%3};"
        : "+f"(d[0]), "+f"(d[1]), "+f"(d[2]), "+f"(d[3])
        : "r"(a[0]), "r"(a[1]), "r"(a[2]), "r"(a[3]), "r"(b0), "r"(b1));
}
__device__ __forceinline__ uint32_t pack_bf2(float lo, float hi) {
    uint32_t r;
    asm("cvt.rn.bf16x2.f32 %0, %1, %2;" : "=r"(r) : "f"(hi), "f"(lo));
    return r;
}
__device__ __forceinline__ void split2(float x, float& h, float& l) {
    h = __bfloat162float(__float2bfloat16(x));
    l = x - h;
}
__device__ __forceinline__ void cpa16(uint32_t dst, const void* src) {
    asm volatile("cp.async.cg.shared.global [%0], [%1], 16;" :: "r"(dst), "l"(src));
}
__device__ __forceinline__ void cp_commit() { asm volatile("cp.async.commit_group;"); }
template<int NW> __device__ __forceinline__ void cp_wait() {
    asm volatile("cp.async.wait_group %0;" :: "n"(NW));
}

// =====================================================================
//   split kernels
// =====================================================================
__global__ void split_mat(const float* __restrict__ src, __nv_bfloat16* __restrict__ dh,
                          __nv_bfloat16* __restrict__ dl, size_t n) {
    size_t i = ((size_t)blockIdx.x*256 + threadIdx.x)*4;
    if (i >= n) return;
    float4 v = *(const float4*)&src[i];
    float hx, lx, hy, ly, hz, lz, hw, lw;
    split2(v.x, hx, lx); split2(v.y, hy, ly); split2(v.z, hz, lz); split2(v.w, hw, lw);
    *(uint2*)&dh[i] = make_uint2(pack_bf2(hx, hy), pack_bf2(hz, hw));
    *(uint2*)&dl[i] = make_uint2(pack_bf2(lx, ly), pack_bf2(lz, lw));
}
__global__ void split_strided(const float* __restrict__ src, int ld,
                              __nv_bfloat16* __restrict__ dh, __nv_bfloat16* __restrict__ dl) {
    size_t i = ((size_t)blockIdx.x*256 + threadIdx.x)*4;
    int row = (int)(i >> 9), col = (int)(i & 511);
    float4 v = *(const float4*)&src[(size_t)row*ld + col];
    float hx, lx, hy, ly, hz, lz, hw, lw;
    split2(v.x, hx, lx); split2(v.y, hy, ly); split2(v.z, hz, lz); split2(v.w, hw, lw);
    *(uint2*)&dh[i] = make_uint2(pack_bf2(hx, hy), pack_bf2(hz, hw));
    *(uint2*)&dl[i] = make_uint2(pack_bf2(lx, ly), pack_bf2(lz, lw));
}
__global__ void to_half(const float* __restrict__ src, __half* __restrict__ dst, size_t n) {
    size_t i = ((size_t)blockIdx.x*256 + threadIdx.x)*4;
    if (i >= n) return;
    float4 v = *(const float4*)&src[i];
    __half2 a = __floats2half2_rn(v.x, v.y), b = __floats2half2_rn(v.z, v.w);
    *(uint2*)&dst[i] = make_uint2(*(uint32_t*)&a, *(uint32_t*)&b);
}

// =====================================================================
//   bf16 3-pass GEMM (NT), cp.async double-buffered — for gi + logits
// =====================================================================
#define KTILE 32
#define LDA   80
#define PLANE 10240
#define STAGE (4*PLANE)
#define SMEM_REQ (2*STAGE + 1024)

__global__ void __launch_bounds__(256) mma_gemm_nt(
        const __nv_bfloat16* __restrict__ Ah, const __nv_bfloat16* __restrict__ Al,
        const __nv_bfloat16* __restrict__ Bh, const __nv_bfloat16* __restrict__ Bl,
        float* __restrict__ C, int M, int N, int K, int ldb,
        const float* __restrict__ bias, const float* __restrict__ rowaux) {
    extern __shared__ char dsm[];
    char* base = (char*)((((uintptr_t)dsm) + 1023) & ~(uintptr_t)1023);
    uint32_t sb0 = smem_u32(base);

    int m0 = blockIdx.y * 128, n0 = blockIdx.x * 128;
    int tid = threadIdx.x;
    int lane = tid & 31, wid = tid >> 5;
    int warp_m = wid & 3, warp_n = wid >> 2;

    float acc[2][8][4];
#pragma unroll
    for (int i = 0; i < 2; i++)
#pragma unroll
        for (int j = 0; j < 8; j++)
#pragma unroll
            for (int q = 0; q < 4; q++) acc[i][j][q] = 0.f;

    int KT = K / KTILE;

    auto load_stage = [&](int s, int kt) {
        uint32_t st = sb0 + s*STAGE;
        uint32_t ah_s = st, al_s = st + PLANE, bh_s = st + 2*PLANE, bl_s = st + 3*PLANE;
        int k0 = kt * KTILE;
#pragma unroll
        for (int i = 0; i < 2; i++) {
            int idx = tid + i*256;
            int row = idx >> 2, kc = idx & 3;
            uint32_t doff = row*LDA + kc*16;
            cpa16(ah_s + doff, Ah + (size_t)(m0 + row)*K + k0 + kc*8);
            cpa16(al_s + doff, Al + (size_t)(m0 + row)*K + k0 + kc*8);
            cpa16(bh_s + doff, Bh + (size_t)(n0 + row)*ldb + k0 + kc*8);
            cpa16(bl_s + doff, Bl + (size_t)(n0 + row)*ldb + k0 + kc*8);
        }
        cp_commit();
    };

    load_stage(0, 0);
    for (int kt = 0; kt < KT; kt++) {
        if (kt + 1 < KT) { load_stage((kt + 1) & 1, kt + 1); cp_wait<1>(); }
        else             { cp_wait<0>(); }
        __syncthreads();
        uint32_t st = sb0 + (kt & 1)*STAGE;
        uint32_t ah_b = st, al_b = st + PLANE, bh_b = st + 2*PLANE, bl_b = st + 3*PLANE;
#pragma unroll
        for (int ks = 0; ks < 2; ks++) {
            int kb = ks*16;
            uint32_t aH[2][4], aL[2][4];
#pragma unroll
            for (int im = 0; im < 2; im++) {
                int row = warp_m*32 + im*16 + (lane & 15);
                uint32_t off = row*LDA + (kb + (lane >> 4)*8)*2;
                ldsm4(aH[im], ah_b + off);
                ldsm4(aL[im], al_b + off);
            }
#pragma unroll
            for (int nc = 0; nc < 4; nc++) {
                uint32_t bH[4], bL[4];
                int row = warp_n*64 + nc*16 + (lane & 15);
                uint32_t off = row*LDA + (kb + (lane >> 4)*8)*2;
                ldsm4(bH, bh_b + off);
                ldsm4(bL, bl_b + off);
#pragma unroll
                for (int im = 0; im < 2; im++) {
                    float* a0 = acc[im][nc*2];
                    float* a1 = acc[im][nc*2 + 1];
                    mma_bf(a0, aH[im], bH[0], bH[2]);
                    mma_bf(a0, aH[im], bL[0], bL[2]);
                    mma_bf(a0, aL[im], bH[0], bH[2]);
                    mma_bf(a1, aH[im], bH[1], bH[3]);
                    mma_bf(a1, aH[im], bL[1], bL[3]);
                    mma_bf(a1, aL[im], bH[1], bH[3]);
                }
            }
        }
        __syncthreads();
    }

    int rbase = m0 + warp_m*32 + (lane >> 2);
    int cbase = n0 + warp_n*64 + (lane & 3)*2;
#pragma unroll
    for (int im = 0; im < 2; im++) {
#pragma unroll
        for (int nf = 0; nf < 8; nf++) {
            int m = rbase + im*16;
            int n = cbase + nf*8;
            float v0 = acc[im][nf][0], v1 = acc[im][nf][1];
            float v2 = acc[im][nf][2], v3 = acc[im][nf][3];
            if (bias)   { float b0 = bias[n], b1 = bias[n+1]; v0 += b0; v1 += b1; v2 += b0; v3 += b1; }
            if (rowaux) {
                float r0 = rowaux[(size_t)(m >> 5)*N + n],     r1 = rowaux[(size_t)(m >> 5)*N + n + 1];
                float r2 = rowaux[(size_t)((m+8) >> 5)*N + n], r3 = rowaux[(size_t)((m+8) >> 5)*N + n + 1];
                v0 += r0; v1 += r1; v2 += r2; v3 += r3;
            }
            *(float2*)&C[(size_t)m*N + n]     = make_float2(v0, v1);
            *(float2*)&C[(size_t)(m+8)*N + n] = make_float2(v2, v3);
        }
    }
}

// =====================================================================
//   fp16 single-pass GEMM (NN) with fused per-row stats — pointwise conv
//   C[m][n] = sum_k A[m][k]*B[k][n]; C stored fp16; row sums -> part2
// =====================================================================
#define HKT 64
#define HLDA 144
#define HLDB 272
#define HPA (128*HLDA)
#define HPB (64*HLDB)
#define HSTAGE (HPA + HPB)
#define HSMEM_REQ (2*HSTAGE + 1024)

__global__ void __launch_bounds__(256) hgemm_nn(
        const __half* __restrict__ A, const __half* __restrict__ B,
        __half* __restrict__ C, double2* __restrict__ part,
        int M, int N, int K, int ldb, size_t strideB, size_t strideC) {
    extern __shared__ char dsm[];
    char* base = (char*)((((uintptr_t)dsm) + 1023) & ~(uintptr_t)1023);
    uint32_t sb0 = smem_u32(base);

    const __half* Bb = B + (size_t)blockIdx.z * strideB;
    __half* Cb = C + (size_t)blockIdx.z * strideC;
    int m0 = blockIdx.y * 128, n0 = blockIdx.x * 128;
    int tid = threadIdx.x;
    int lane = tid & 31, wid = tid >> 5;
    int warp_m = wid & 3, warp_n = wid >> 2;

    float acc[2][8][4];
#pragma unroll
    for (int i = 0; i < 2; i++)
#pragma unroll
        for (int j = 0; j < 8; j++)
#pragma unroll
            for (int q = 0; q < 4; q++) acc[i][j][q] = 0.f;

    int KT = K / HKT;   // 4

    auto load_stage = [&](int s, int kt) {
        uint32_t st = sb0 + s*HSTAGE;
        uint32_t as = st, bs = st + HPA;
        int k0 = kt * HKT;
#pragma unroll
        for (int i = 0; i < 4; i++) {
            int idx = tid + i*256;
            int row = idx >> 3, kc = idx & 7;
            cpa16(as + row*HLDA + kc*16, A + (size_t)(m0 + row)*K + k0 + kc*8);
        }
#pragma unroll
        for (int i = 0; i < 4; i++) {
            int idx = tid + i*256;
            int row = idx >> 4, c = idx & 15;
            cpa16(bs + row*HLDB + c*16, Bb + (size_t)(k0 + row)*ldb + n0 + c*8);
        }
        cp_commit();
    };

    load_stage(0, 0);
    for (int kt = 0; kt < KT; kt++) {
        if (kt + 1 < KT) { load_stage((kt + 1) & 1, kt + 1); cp_wait<1>(); }
        else             { cp_wait<0>(); }
        __syncthreads();
        uint32_t st = sb0 + (kt & 1)*HSTAGE;
        uint32_t as = st, bs = st + HPA;
#pragma unroll
        for (int ks = 0; ks < 4; ks++) {
            int kb = ks*16;
            uint32_t aF[2][4];
#pragma unroll
            for (int im = 0; im < 2; im++) {
                int row = warp_m*32 + im*16 + (lane & 15);
                uint32_t off = row*HLDA + (kb + (lane >> 4)*8)*2;
                ldsm4(aF[im], as + off);
            }
#pragma unroll
            for (int nc = 0; nc < 4; nc++) {
                uint32_t bF[4];
                int row = kb + (lane & 15);
                int col = warp_n*64 + nc*16 + (lane >> 4)*8;
                ldsm4t(bF, bs + row*HLDB + col*2);
#pragma unroll
                for (int im = 0; im < 2; im++) {
                    mma_fp(acc[im][nc*2],     aF[im], bF[0], bF[1]);
                    mma_fp(acc[im][nc*2 + 1], aF[im], bF[2], bF[3]);
                }
            }
        }
        __syncthreads();
    }

    // ---- epilogue: fp16 store + per-row (channel) sum/sumsq ----
    int rloc = warp_m*32 + (lane >> 2);
    int cbase = n0 + warp_n*64 + (lane & 3)*2;
    float s[4]  = {0.f, 0.f, 0.f, 0.f};
    float s2[4] = {0.f, 0.f, 0.f, 0.f};
#pragma unroll
    for (int im = 0; im < 2; im++) {
#pragma unroll
        for (int nf = 0; nf < 8; nf++) {
            int m = m0 + rloc + im*16;
            int n = cbase + nf*8;
            float v0 = acc[im][nf][0], v1 = acc[im][nf][1];
            float v2 = acc[im][nf][2], v3 = acc[im][nf][3];
            __half2 h01 = __floats2half2_rn(v0, v1);
            __half2 h23 = __floats2half2_rn(v2, v3);
            *(__half2*)&Cb[(size_t)m*N + n]     = h01;
            *(__half2*)&Cb[(size_t)(m+8)*N + n] = h23;
            s [im*2+0] += v0 + v1;    s2[im*2+0] += v0*v0 + v1*v1;
            s [im*2+1] += v2 + v3;    s2[im*2+1] += v2*v2 + v3*v3;
        }
    }
#pragma unroll
    for (int r = 0; r < 4; r++) {
        s [r] += __shfl_xor_sync(0xffffffffu, s [r], 1);
        s [r] += __shfl_xor_sync(0xffffffffu, s [r], 2);
        s2[r] += __shfl_xor_sync(0xffffffffu, s2[r], 1);
        s2[r] += __shfl_xor_sync(0xffffffffu, s2[r], 2);
    }
    float2* sst = (float2*)base;   // [2][128]
    __syncthreads();
    if ((lane & 3) == 0) {
#pragma unroll
        for (int r = 0; r < 4; r++) {
            int row = rloc + (r >> 1)*16 + (r & 1)*8;
            sst[warp_n*128 + row] = make_float2(s[r], s2[r]);
        }
    }
    __syncthreads();
    if (tid < 128) {
        float2 a = sst[tid], b = sst[128 + tid];
        double2 p;
        p.x = (double)a.x + (double)b.x;
        p.y = (double)a.y + (double)b.y;
        part[(size_t)(m0 + tid)*(BSZ*98) + blockIdx.z*98 + blockIdx.x] = p;
    }
}

// finalize BN2 scale/shift from fused partials; warp per channel
__global__ void chan_finalize2(const double2* __restrict__ part,
                               const float* __restrict__ g, const float* __restrict__ bt,
                               float* __restrict__ scale, float* __restrict__ shift) {
    int warp = (blockIdx.x*256 + threadIdx.x) >> 5;
    int lane = threadIdx.x & 31;
    if (warp >= C2) return;
    double s = 0, s2 = 0;
    for (int i = lane; i < BSZ*98; i += 32) {
        double2 p = part[(size_t)warp*(BSZ*98) + i];
        s += p.x; s2 += p.y;
    }
#pragma unroll
    for (int o = 16; o; o >>= 1) {
        s  += __shfl_xor_sync(0xffffffffu, s,  o);
        s2 += __shfl_xor_sync(0xffffffffu, s2, o);
    }
    if (lane == 0) {
        double cnt = (double)BSZ * HW;
        double m = s / cnt;
        double var = s2 / cnt - m*m;
        float rs = (float)(1.0 / sqrt(var + 1e-5));
        float sc = g[warp] * rs;
        scale[warp] = sc;
        shift[warp] = bt[warp] - (float)m * sc;
    }
}

// ---------------- conv1: 3->256, 3x3 s2 p1; transposed weights + 4-ch inner ----
__global__ void conv1_kernel(const float* __restrict__ img, const float* __restrict__ w,
                             float* __restrict__ out) {
    __shared__ float ws[27][256];
    int b = blockIdx.y;
    int tY = blockIdx.x / 7, tX = blockIdx.x % 7;
    for (int i = threadIdx.x; i < C1*27; i += 256) {
        int c = i / 27, k = i - c*27;
        ws[k][c] = w[i];
    }
    __syncthreads();
    int ty = threadIdx.x >> 4, tx = threadIdx.x & 15;
    int oy = tY*16 + ty, ox = tX*16 + tx;
    int iy0 = oy*2 - 1, ix0 = ox*2 - 1;
    const float* ip = img + (size_t)b*3*224*224;
    float v[27];
#pragma unroll
    for (int ci = 0; ci < 3; ci++)
#pragma unroll
        for (int ky = 0; ky < 3; ky++)
#pragma unroll
            for (int kx = 0; kx < 3; kx++) {
                int iy = iy0 + ky, ix = ix0 + kx;
                float t = 0.f;
                if (iy >= 0 && iy < 224 && ix >= 0 && ix < 224)
                    t = ip[(ci*224 + iy)*224 + ix];
                v[ci*9 + ky*3 + kx] = t;
            }
    size_t obase = (size_t)b*C1*HW + oy*112 + ox;
    for (int c4 = 0; c4 < 64; c4++) {
        float4 a = make_float4(0.f, 0.f, 0.f, 0.f);
#pragma unroll
        for (int k = 0; k < 27; k++) {
            float4 wv = *(const float4*)&ws[k][c4*4];
            a.x += v[k]*wv.x; a.y += v[k]*wv.y; a.z += v[k]*wv.z; a.w += v[k]*wv.w;
        }
        out[obase + (size_t)(c4*4+0)*HW] = a.x;
        out[obase + (size_t)(c4*4+1)*HW] = a.y;
        out[obase + (size_t)(c4*4+2)*HW] = a.z;
        out[obase + (size_t)(c4*4+3)*HW] = a.w;
    }
}

// ---------------- per-channel stats for conv1 (two-stage, double) ----------------
__global__ void chan_partial(const float* __restrict__ x, int C, double* __restrict__ part) {
    int c = blockIdx.x, b = blockIdx.y;
    const float* p = x + ((size_t)b*C + c)*HW;
    double s = 0, s2 = 0;
    for (int i = threadIdx.x; i < HW; i += 256) { double v = p[i]; s += v; s2 += v*v; }
    __shared__ double sh[256], sh2[256];
    sh[threadIdx.x] = s; sh2[threadIdx.x] = s2; __syncthreads();
    for (int o = 128; o; o >>= 1) {
        if (threadIdx.x < o) { sh[threadIdx.x] += sh[threadIdx.x+o]; sh2[threadIdx.x] += sh2[threadIdx.x+o]; }
        __syncthreads();
    }
    if (threadIdx.x == 0) { part[(c*BSZ + b)*2] = sh[0]; part[(c*BSZ + b)*2 + 1] = sh2[0]; }
}
__global__ void chan_finalize(int C, const double* __restrict__ part,
                              const float* __restrict__ g, const float* __restrict__ bt,
                              float* __restrict__ scale, float* __restrict__ shift) {
    int c = blockIdx.x*blockDim.x + threadIdx.x;
    if (c >= C) return;
    double s = 0, s2 = 0;
    for (int b = 0; b < BSZ; b++) { s += part[(c*BSZ+b)*2]; s2 += part[(c*BSZ+b)*2 + 1]; }
    double cnt = (double)BSZ * HW;
    double m = s / cnt;
    double var = s2 / cnt - m*m;
    float rs = (float)(1.0 / sqrt(var + 1e-5));
    float sc = g[c] * rs;
    scale[c] = sc;
    shift[c] = bt[c] - (float)m * sc;
}

// ---------------- depthwise 3x3 s1 p1 (BN1+ReLU fused), writes fp16 -------------
__global__ void dw_kernel(const float* __restrict__ in, const float* __restrict__ w,
                          const float* __restrict__ scale, const float* __restrict__ shift,
                          __half* __restrict__ outh) {
    int warp = threadIdx.x >> 5, lane = threadIdx.x & 31;
    int y = blockIdx.x*8 + warp;
    int c = blockIdx.y, b = blockIdx.z;
    float sc = scale[c], sh = shift[c];
    const float* ip = in + ((size_t)b*C1 + c)*HW;
    int x0 = lane*4;
    bool inx = (x0 < 112);

    float v[3][4];
    float lft[3], rgt[3];
#pragma unroll
    for (int r = 0; r < 3; r++) {
        int yy = y - 1 + r;
        float4 t = make_float4(0.f, 0.f, 0.f, 0.f);
        if (inx && yy >= 0 && yy < 112)
            t = *(const float4*)&ip[yy*112 + x0];
        v[r][0] = fmaxf(t.x*sc + sh, 0.f);
        v[r][1] = fmaxf(t.y*sc + sh, 0.f);
        v[r][2] = fmaxf(t.z*sc + sh, 0.f);
        v[r][3] = fmaxf(t.w*sc + sh, 0.f);
        if (!inx || yy < 0 || yy >= 112) { v[r][0]=v[r][1]=v[r][2]=v[r][3]=0.f; }
        lft[r] = __shfl_up_sync(0xffffffffu, v[r][3], 1);
        if (lane == 0) lft[r] = 0.f;
        rgt[r] = __shfl_down_sync(0xffffffffu, v[r][0], 1);
        if (lane >= 27) rgt[r] = 0.f;
    }
    float wv[9];
#pragma unroll
    for (int k = 0; k < 9; k++) wv[k] = __ldg(&w[c*9 + k]);

    float o0 = 0.f, o1 = 0.f, o2 = 0.f, o3 = 0.f;
#pragma unroll
    for (int r = 0; r < 3; r++) {
        float e0 = lft[r], e1 = v[r][0], e2 = v[r][1], e3 = v[r][2], e4 = v[r][3], e5 = rgt[r];
        float w0 = wv[r*3+0], w1 = wv[r*3+1], w2 = wv[r*3+2];
        o0 += w0*e0 + w1*e1 + w2*e2;
        o1 += w0*e1 + w1*e2 + w2*e3;
        o2 += w0*e2 + w1*e3 + w2*e4;
        o3 += w0*e3 + w1*e4 + w2*e5;
    }
    if (inx) {
        __half2 h01 = __floats2half2_rn(o0, o1);
        __half2 h23 = __floats2half2_rn(o2, o3);
        size_t off = ((size_t)b*C1 + c)*HW + y*112 + x0;
        *(uint2*)&outh[off] = make_uint2(*(uint32_t*)&h01, *(uint32_t*)&h23);
    }
}

// ---------------- pooled[b][c] = mean_p relu(bn2(pw)), fp16 source ----------------
__global__ void pooled_kernel(const __half* __restrict__ x, const float* __restrict__ scale,
                              const float* __restrict__ shift, float* __restrict__ pooled) {
    int c = blockIdx.x, b = blockIdx.y;
    const __half* p = x + ((size_t)b*C2 + c)*HW;
    float sc = scale[c], sh = shift[c];
    double s = 0;
    for (int i = threadIdx.x; i < HW; i += 256) {
        float v = __half2float(p[i])*sc + sh;
        if (v > 0.f) s += v;
    }
    __shared__ double shm[256];
    shm[threadIdx.x] = s; __syncthreads();
    for (int o = 128; o; o >>= 1) {
        if (threadIdx.x < o) shm[threadIdx.x] += shm[threadIdx.x+o];
        __syncthreads();
    }
    if (threadIdx.x == 0) pooled[b*C2 + c] = (float)(shm[0] / (double)HW);
}

// ---------------- small GEMM ----------------
__global__ void small_gemm(const float* __restrict__ in, int K,
                           const float* __restrict__ W, int ldw, int woff,
                           const float* __restrict__ bias, const float* __restrict__ aux,
                           int O, int act, float* __restrict__ out) {
    __shared__ float sin_s[BSZ*512];
    for (int i = threadIdx.x; i < BSZ*K; i += 256) sin_s[i] = in[i];
    __syncthreads();
    int warp = threadIdx.x >> 5, lane = threadIdx.x & 31;
    int o = blockIdx.x*8 + warp;
    float part[BSZ];
#pragma unroll
    for (int b = 0; b < BSZ; b++) part[b] = 0.f;
    for (int k = lane; k < K; k += 32) {
        float wv = W[(size_t)o*ldw + woff + k];
#pragma unroll
        for (int b = 0; b < BSZ; b++) part[b] += wv * sin_s[b*K + k];
    }
#pragma unroll
    for (int b = 0; b < BSZ; b++) {
        float v = part[b];
#pragma unroll
        for (int off = 16; off; off >>= 1) v += __shfl_xor_sync(0xffffffffu, v, off);
        if (lane == b) {
            if (bias) v += bias[o];
            if (act == 1) v = v > 0.f ? v : 0.f;
            else if (act == 2) v = (1.f/(1.f + expf(-v))) * aux[b*O + o];
            out[b*O + o] = v;
        }
    }
}

// ---------------- gather caption embeddings: split planes ----------------
__global__ void gather_embs(const int* __restrict__ cap, const float* __restrict__ embed,
                            __nv_bfloat16* __restrict__ eh, __nv_bfloat16* __restrict__ el) {
    int row = blockIdx.x;
    int b = row >> 5, t = row & 31;
    int tok = cap[b*33 + t];
    const float* src = embed + (size_t)tok*HID;
    int i = threadIdx.x*2;
    float2 v = *(const float2*)&src[i];
    float h0,l0,h1,l1;
    split2(v.x,h0,l0); split2(v.y,h1,l1);
    *(uint32_t*)&eh[(size_t)row*HID + i] = pack_bf2(h0,h1);
    *(uint32_t*)&el[(size_t)row*HID + i] = pack_bf2(l0,l1);
}

// ---------------- persistent GRU ----------------
__global__ void gru_reset() {
    if (threadIdx.x < TT) g_gbar[threadIdx.x] = 0;
}
#define GRU_BLKS 64
__global__ void __launch_bounds__(256) gru_persist(
        const float* __restrict__ gi, const float* __restrict__ whh,
        const float* __restrict__ bhh, float* __restrict__ hall,
        __nv_bfloat16* __restrict__ hallh, __nv_bfloat16* __restrict__ halll) {
    __shared__ float hs[BSZ*HID];
    int tid = threadIdx.x;
    int warp = tid >> 5, lane = tid & 31;
    int j = blockIdx.x*8 + warp;
    float w0[16], w1[16], w2[16];
#pragma unroll
    for (int i = 0; i < 16; i++) {
        int k = lane + 32*i;
        w0[i] = whh[(size_t)j*HID + k];
        w1[i] = whh[(size_t)(j + 512)*HID + k];
        w2[i] = whh[(size_t)(j + 1024)*HID + k];
    }
    float bhr = bhh[j], bhz = bhh[j + 512], bhn = bhh[j + 1024];

    for (int t = 0; t < TT; t++) {
        for (int i = tid; i < BSZ*HID; i += 256) {
            int b = i >> 9, jj = i & 511;
            hs[i] = (t == 0) ? 0.f : hall[((size_t)(b*TT + t - 1))*HID + jj];
        }
        __syncthreads();
        for (int b = 0; b < BSZ; b++) {
            float pr = 0.f, pz = 0.f, pn = 0.f;
#pragma unroll
            for (int i = 0; i < 16; i++) {
                float hv = hs[b*HID + lane + 32*i];
                pr += hv*w0[i]; pz += hv*w1[i]; pn += hv*w2[i];
            }
#pragma unroll
            for (int o = 16; o; o >>= 1) {
                pr += __shfl_xor_sync(0xffffffffu, pr, o);
                pz += __shfl_xor_sync(0xffffffffu, pz, o);
                pn += __shfl_xor_sync(0xffffffffu, pn, o);
            }
            if (lane == 0) {
                size_t gib = ((size_t)(b*TT + t))*1536;
                float ir = gi[gib + j], iz = gi[gib + 512 + j], inn = gi[gib + 1024 + j];
                float r = 1.f/(1.f + expf(-(ir + pr + bhr)));
                float z = 1.f/(1.f + expf(-(iz + pz + bhz)));
                float n = tanhf(inn + r*(pn + bhn));
                float hp = hs[b*HID + j];
                float hn2 = (1.f - z)*n + z*hp;
                size_t oidx = ((size_t)(b*TT + t))*HID + j;
                hall[oidx] = hn2;
                float hh, hl;
                split2(hn2, hh, hl);
                hallh[oidx] = __float2bfloat16(hh);
                halll[oidx] = __float2bfloat16(hl);
            }
        }
        __threadfence();
        __syncthreads();
        if (tid == 0) {
            atomicAdd(&g_gbar[t], 1);
            while (atomicAdd(&g_gbar[t], 0) < GRU_BLKS) __nanosleep(64);
        }
        __syncthreads();
    }
}

// =======================================================================
extern "C" void kernel_launch(void* const* d_in, const int* in_sizes, int n_in,
                              void* d_out, int out_size) {
    const float* images   = (const float*)d_in[0];
    const int*   captions = (const int*)  d_in[1];
    const float* conv1_w  = (const float*)d_in[2];
    const float* bn1_g    = (const float*)d_in[3];
    const float* bn1_b    = (const float*)d_in[4];
    const float* dw_w     = (const float*)d_in[5];
    const float* pw_w     = (const float*)d_in[6];
    const float* bn2_g    = (const float*)d_in[7];
    const float* bn2_b    = (const float*)d_in[8];
    const float* se_fc1_w = (const float*)d_in[9];
    const float* se_fc2_w = (const float*)d_in[10];
    const float* enc_fc_w = (const float*)d_in[11];
    const float* enc_fc_b = (const float*)d_in[12];
    const float* embed    = (const float*)d_in[13];
    // d_in[14] = q_w (unused), d_in[15] = k_w (unused)
    const float* v_w      = (const float*)d_in[16];
    const float* gru_w_ih = (const float*)d_in[17];
    const float* gru_w_hh = (const float*)d_in[18];
    const float* gru_b_ih = (const float*)d_in[19];
    const float* gru_b_hh = (const float*)d_in[20];
    const float* fc_w     = (const float*)d_in[21];
    const float* fc_b     = (const float*)d_in[22];

    float *conv1buf;
    double *part;
    double2 *part2;
    float *scale1, *shift1, *scale2, *shift2;
    float *pooled, *t1, *fbuf, *feats, *ctx, *gctx, *gi, *hall;
    __half *dwh, *pwwh, *pwout;
    __nv_bfloat16 *fcwh, *fcwl, *wihh, *wihl, *embsh, *embsl, *hallh, *halll;
    cudaGetSymbolAddress((void**)&conv1buf, g_conv1);
    cudaGetSymbolAddress((void**)&part,     g_part);
    cudaGetSymbolAddress((void**)&part2,    g_part2);
    cudaGetSymbolAddress((void**)&scale1,   g_scale1);
    cudaGetSymbolAddress((void**)&shift1,   g_shift1);
    cudaGetSymbolAddress((void**)&scale2,   g_scale2);
    cudaGetSymbolAddress((void**)&shift2,   g_shift2);
    cudaGetSymbolAddress((void**)&pooled,   g_pooled);
    cudaGetSymbolAddress((void**)&t1,       g_t1);
    cudaGetSymbolAddress((void**)&fbuf,     g_f);
    cudaGetSymbolAddress((void**)&feats,    g_feats);
    cudaGetSymbolAddress((void**)&ctx,      g_ctx);
    cudaGetSymbolAddress((void**)&gctx,     g_gctx);
    cudaGetSymbolAddress((void**)&gi,       g_gi);
    cudaGetSymbolAddress((void**)&hall,     g_hall);
    cudaGetSymbolAddress((void**)&dwh,      g_dwh);
    cudaGetSymbolAddress((void**)&pwwh,     g_pwwh);
    cudaGetSymbolAddress((void**)&pwout,    g_pwout);
    cudaGetSymbolAddress((void**)&fcwh,     g_fcwh);
    cudaGetSymbolAddress((void**)&fcwl,     g_fcwl);
    cudaGetSymbolAddress((void**)&wihh,     g_wihh);
    cudaGetSymbolAddress((void**)&wihl,     g_wihl);
    cudaGetSymbolAddress((void**)&embsh,    g_embsh);
    cudaGetSymbolAddress((void**)&embsl,    g_embsl);
    cudaGetSymbolAddress((void**)&hallh,    g_hallh);
    cudaGetSymbolAddress((void**)&halll,    g_halll);

    cudaFuncSetAttribute(mma_gemm_nt, cudaFuncAttributeMaxDynamicSharedMemorySize, SMEM_REQ);
    cudaFuncSetAttribute(hgemm_nn,    cudaFuncAttributeMaxDynamicSharedMemorySize, HSMEM_REQ);

    // weight conversions (independent of encoder)
    to_half<<<(C2*C1)/1024, 256>>>(pw_w, pwwh, (size_t)C2*C1);
    split_mat<<<((size_t)VOC*HID)/1024, 256>>>(fc_w, fcwh, fcwl, (size_t)VOC*HID);
    split_strided<<<(1536*512)/1024, 256>>>(gru_w_ih, 1024, wihh, wihl);

    // encoder
    conv1_kernel<<<dim3(49, BSZ), 256>>>(images, conv1_w, conv1buf);
    chan_partial<<<dim3(C1, BSZ), 256>>>(conv1buf, C1, part);
    chan_finalize<<<1, 256>>>(C1, part, bn1_g, bn1_b, scale1, shift1);
    dw_kernel<<<dim3(14, C1, BSZ), 256>>>(conv1buf, dw_w, scale1, shift1, dwh);
    // pointwise conv (fp16 single-pass GEMM, fused BN2 stats)
    hgemm_nn<<<dim3(98, 4, BSZ), 256, HSMEM_REQ>>>(pwwh, dwh, pwout, part2,
                                                   C2, HW, C1, HW,
                                                   (size_t)C1*HW, (size_t)C2*HW);
    chan_finalize2<<<64, 256>>>(part2, bn2_g, bn2_b, scale2, shift2);
    pooled_kernel<<<dim3(C2, BSZ), 256>>>(pwout, scale2, shift2, pooled);

    // SE + encoder FC + ctx (tiny GEMMs)
    small_gemm<<<16, 256>>>(pooled, 512, se_fc1_w, 512, 0, nullptr, nullptr, 128, 1, t1);
    small_gemm<<<64, 256>>>(t1, 128, se_fc2_w, 128, 0, nullptr, pooled, 512, 2, fbuf);
    small_gemm<<<64, 256>>>(fbuf, 512, enc_fc_w, 512, 0, enc_fc_b, nullptr, 512, 0, feats);
    small_gemm<<<64, 256>>>(feats, 512, v_w, 512, 0, nullptr, nullptr, 512, 0, ctx);

    // decoder: precompute input gates
    small_gemm<<<192, 256>>>(ctx, 512, gru_w_ih, 1024, 512, gru_b_ih, nullptr, 1536, 0, gctx);
    gather_embs<<<512, 256>>>(captions, embed, embsh, embsl);
    mma_gemm_nt<<<dim3(12, 4, 1), 256, SMEM_REQ>>>(embsh, embsl, wihh, wihl, gi,
                                                   512, 1536, 512, 512, nullptr, gctx);

    // persistent GRU recurrence
    gru_reset<<<1, 32>>>();
    gru_persist<<<GRU_BLKS, 256>>>(gi, gru_w_hh, gru_b_hh, hall, hallh, halll);

    // logits: 3-pass bf16 (precision-critical, lands directly in output)
    mma_gemm_nt<<<dim3(250, 4, 1), 256, SMEM_REQ>>>(hallh, halll, fcwh, fcwl, (float*)d_out,
                                                    512, VOC, 512, 512, fc_b, nullptr);
}